// round 13
// baseline (speedup 1.0000x reference)
#include <cuda_runtime.h>
#include <cuda_bf16.h>
#include <math.h>
#include <stdint.h>

// Problem constants
#define Bb 2
#define Tt 1024
#define Ee 2048
#define Hh 16
#define Dd 64
#define H2 32          // 2*H
#define D2 128         // 2*D
#define Mm (Bb*Tt)     // 2048
#define LAMBDA_INIT 0.78360576653162f
#define EPS_RMS 1e-5f

// ------------------------ scratch (static device memory) ------------------------
__device__ float g_qraw[(size_t)Mm*Ee];
__device__ float g_kraw[(size_t)Mm*Ee];
__device__ float g_oc[(size_t)Bb*H2*Tt*D2];   // per-component attention output
__device__ float g_lam[1];
__device__ float g_cos[Tt*32];
__device__ float g_sin[Tt*32];

// bf16 split buffers
__device__ __nv_bfloat16 g_xhi[(size_t)Mm*Ee];
__device__ __nv_bfloat16 g_xlo[(size_t)Mm*Ee];
__device__ __nv_bfloat16 g_whi[(size_t)4*Ee*Ee];
__device__ __nv_bfloat16 g_wlo[(size_t)4*Ee*Ee];
__device__ __nv_bfloat16 g_yhi[(size_t)Mm*Ee];
__device__ __nv_bfloat16 g_ylo[(size_t)Mm*Ee];
// rope'd q/k in (B,2H,T,D), hi/lo split
__device__ __nv_bfloat16 g_qhib[(size_t)Bb*H2*Tt*Dd];
__device__ __nv_bfloat16 g_qlob[(size_t)Bb*H2*Tt*Dd];
__device__ __nv_bfloat16 g_khib[(size_t)Bb*H2*Tt*Dd];
__device__ __nv_bfloat16 g_klob[(size_t)Bb*H2*Tt*Dd];
// v split in (b,t,e) -- written directly by the QKV GEMM epilogue
__device__ __nv_bfloat16 g_vhib[(size_t)Mm*Ee];
__device__ __nv_bfloat16 g_vlob[(size_t)Mm*Ee];

// ------------------------ helpers ------------------------
__device__ __forceinline__ unsigned s2u(const void* p) {
    return (unsigned)__cvta_generic_to_shared(p);
}
__device__ __forceinline__ void cp16(unsigned saddr, const void* g) {
    asm volatile("cp.async.cg.shared.global [%0], [%1], 16;\n" :: "r"(saddr), "l"(g));
}
#define CP_COMMIT() asm volatile("cp.async.commit_group;\n" ::: "memory")
#define CP_WAIT0()  asm volatile("cp.async.wait_group 0;\n" ::: "memory")

#define LDSM4(r, addr) \
    asm volatile("ldmatrix.sync.aligned.m8n8.x4.shared.b16 {%0,%1,%2,%3}, [%4];" \
        : "=r"((r)[0]), "=r"((r)[1]), "=r"((r)[2]), "=r"((r)[3]) : "r"(addr))
#define LDSM4T(r, addr) \
    asm volatile("ldmatrix.sync.aligned.m8n8.x4.trans.shared.b16 {%0,%1,%2,%3}, [%4];" \
        : "=r"((r)[0]), "=r"((r)[1]), "=r"((r)[2]), "=r"((r)[3]) : "r"(addr))

#define MMA_BF16(d, a, b) \
    asm volatile("mma.sync.aligned.m16n8k16.row.col.f32.bf16.bf16.f32 " \
        "{%0,%1,%2,%3}, {%4,%5,%6,%7}, {%8,%9}, {%0,%1,%2,%3};" \
        : "+f"((d)[0]), "+f"((d)[1]), "+f"((d)[2]), "+f"((d)[3]) \
        : "r"((a)[0]), "r"((a)[1]), "r"((a)[2]), "r"((a)[3]), "r"((b)[0]), "r"((b)[1]))

__device__ __forceinline__ unsigned packbf(float a, float b) {
    unsigned short ua = __bfloat16_as_ushort(__float2bfloat16(a));
    unsigned short ub = __bfloat16_as_ushort(__float2bfloat16(b));
    return (unsigned)ua | ((unsigned)ub << 16);
}
// hi/lo split of a pair, packed as 2x bf16 words
__device__ __forceinline__ void store_hl(__nv_bfloat16* hi, __nv_bfloat16* lo,
                                         size_t off, float a, float b) {
    __nv_bfloat16 ha = __float2bfloat16(a), hb = __float2bfloat16(b);
    unsigned hw = (unsigned)__bfloat16_as_ushort(ha) |
                  ((unsigned)__bfloat16_as_ushort(hb) << 16);
    unsigned lw = packbf(a - __bfloat162float(ha), b - __bfloat162float(hb));
    *(unsigned*)(hi + off) = hw;
    *(unsigned*)(lo + off) = lw;
}

// ------------------------ fp32 -> bf16 hi/lo split ------------------------
__device__ __forceinline__ void split4(const float* __restrict__ s,
                                       __nv_bfloat16* __restrict__ hi,
                                       __nv_bfloat16* __restrict__ lo, int i) {
    float4 v = ((const float4*)s)[i];
    __nv_bfloat16 h0 = __float2bfloat16(v.x);
    __nv_bfloat16 h1 = __float2bfloat16(v.y);
    __nv_bfloat16 h2 = __float2bfloat16(v.z);
    __nv_bfloat16 h3 = __float2bfloat16(v.w);
    __nv_bfloat16 l0 = __float2bfloat16(v.x - __bfloat162float(h0));
    __nv_bfloat16 l1 = __float2bfloat16(v.y - __bfloat162float(h1));
    __nv_bfloat16 l2 = __float2bfloat16(v.z - __bfloat162float(h2));
    __nv_bfloat16 l3 = __float2bfloat16(v.w - __bfloat162float(h3));
    ushort4 hv, lv;
    hv.x = __bfloat16_as_ushort(h0); hv.y = __bfloat16_as_ushort(h1);
    hv.z = __bfloat16_as_ushort(h2); hv.w = __bfloat16_as_ushort(h3);
    lv.x = __bfloat16_as_ushort(l0); lv.y = __bfloat16_as_ushort(l1);
    lv.z = __bfloat16_as_ushort(l2); lv.w = __bfloat16_as_ushort(l3);
    ((ushort4*)hi)[i] = hv;
    ((ushort4*)lo)[i] = lv;
}

__global__ __launch_bounds__(256) void cvt_split(const float* __restrict__ s,
                                                 __nv_bfloat16* __restrict__ hi,
                                                 __nv_bfloat16* __restrict__ lo, int n4) {
    int i = blockIdx.x * blockDim.x + threadIdx.x;
    if (i >= n4) return;
    split4(s, hi, lo, i);
}

// all 4 weight matrices in one launch; each is exactly 2^20 float4s
__global__ __launch_bounds__(256) void cvt_split4(
    const float* __restrict__ w0, const float* __restrict__ w1,
    const float* __restrict__ w2, const float* __restrict__ w3,
    __nv_bfloat16* __restrict__ hi, __nv_bfloat16* __restrict__ lo) {
    int idx = blockIdx.x * blockDim.x + threadIdx.x;   // 0 .. 4*2^20-1
    int sel = idx >> 20;
    int i = idx & ((1 << 20) - 1);
    const float* w = (sel == 0) ? w0 : (sel == 1) ? w1 : (sel == 2) ? w2 : w3;
    size_t off = (size_t)sel << 22;                    // sel * Ee*Ee elems
    split4(w, hi + off, lo + off, i);
}

// ------------------------ bf16x3 GEMM core: acc += A[M,K] @ B[N,K]^T tile ------------------------
// BM=BN=128, BK=32(bf16), 256 threads (8 warps 4x2), 2-stage cp.async, 2 CTAs/SM.
// single sync per k-tile: stage it+1 issued right after the barrier into the
// buffer consumed at it-1 (same barrier guarantees all reads done).
#define BM 128
#define BN 128
#define BKg 32
#define KP 40                    // padded bf16 row stride (80B): conflict-free ldmatrix
#define STG (4*128*KP)           // elems per stage: Ahi,Alo,Bhi,Blo
#define GSMEM (2*STG*2)          // 81920 B

__device__ __forceinline__ void gemm_core(
    const __nv_bfloat16* __restrict__ Ahi, const __nv_bfloat16* __restrict__ Alo,
    const __nv_bfloat16* __restrict__ Bhi, const __nv_bfloat16* __restrict__ Blo,
    int row0, int col0, int K,
    __nv_bfloat16* sm, float acc[2][8][4])
{
    const int tid = threadIdx.x;
    const int lane = tid & 31, warp = tid >> 5;
    const int wm = (warp & 3) * 32, wn = (warp >> 2) * 64;
    const int lr = tid >> 2, lq = (tid & 3) * 8;

    const __nv_bfloat16* gbase[4] = {Ahi, Alo, Bhi, Blo};
    const int grow0[4] = {row0, row0, col0, col0};

    auto issue = [&](int buf, int k0) {
        __nv_bfloat16* s = sm + buf * STG;
#pragma unroll
        for (int a = 0; a < 4; a++) {
            const __nv_bfloat16* g = gbase[a] + (size_t)(grow0[a] + lr) * K + k0 + lq;
            cp16(s2u(s + a * 128 * KP + lr * KP + lq), g);
            cp16(s2u(s + a * 128 * KP + (lr + 64) * KP + lq), g + (size_t)64 * K);
        }
        CP_COMMIT();
    };

    issue(0, 0);

    const int niter = K / BKg;
    for (int it = 0; it < niter; it++) {
        CP_WAIT0();
        __syncthreads();                       // stage it&1 visible; buffer (it+1)&1 free
        if (it + 1 < niter) issue((it + 1) & 1, (it + 1) * BKg);

        __nv_bfloat16* s = sm + (it & 1) * STG;
        __nv_bfloat16* sAhi = s;
        __nv_bfloat16* sAlo = s + 128 * KP;
        __nv_bfloat16* sBhi = s + 2 * 128 * KP;
        __nv_bfloat16* sBlo = s + 3 * 128 * KP;

#pragma unroll
        for (int kk = 0; kk < 2; kk++) {
            unsigned afh[2][4], afl[2][4], bfh[4][4], bfl[4][4];
#pragma unroll
            for (int mi = 0; mi < 2; mi++) {
                int r = wm + mi * 16 + (lane & 15);
                int c = kk * 16 + (lane >> 4) * 8;
                LDSM4(afh[mi], s2u(sAhi + r * KP + c));
                LDSM4(afl[mi], s2u(sAlo + r * KP + c));
            }
#pragma unroll
            for (int p = 0; p < 4; p++) {
                int r = wn + p * 16 + ((lane >> 4) & 1) * 8 + (lane & 7);
                int c = kk * 16 + ((lane >> 3) & 1) * 8;
                LDSM4(bfh[p], s2u(sBhi + r * KP + c));
                LDSM4(bfl[p], s2u(sBlo + r * KP + c));
            }
            // pass 1: Ahi * Bhi
#pragma unroll
            for (int mi = 0; mi < 2; mi++)
#pragma unroll
                for (int nj = 0; nj < 8; nj++)
                    MMA_BF16(acc[mi][nj], afh[mi], &bfh[nj >> 1][(nj & 1) * 2]);
            // pass 2: Ahi * Blo
#pragma unroll
            for (int mi = 0; mi < 2; mi++)
#pragma unroll
                for (int nj = 0; nj < 8; nj++)
                    MMA_BF16(acc[mi][nj], afh[mi], &bfl[nj >> 1][(nj & 1) * 2]);
            // pass 3: Alo * Bhi
#pragma unroll
            for (int mi = 0; mi < 2; mi++)
#pragma unroll
                for (int nj = 0; nj < 8; nj++)
                    MMA_BF16(acc[mi][nj], afl[mi], &bfh[nj >> 1][(nj & 1) * 2]);
        }
    }
}

// fused QKV projection: N = 3*2048 over [wq; wk; wv] rows of g_whi
__global__ __launch_bounds__(256, 2) void gemm_qkv() {
    extern __shared__ __align__(16) __nv_bfloat16 sm[];
    const int row0 = blockIdx.y * BM, col0 = blockIdx.x * BN;
    const int lane = threadIdx.x & 31, warp = threadIdx.x >> 5;
    const int wm = (warp & 3) * 32, wn = (warp >> 2) * 64;

    float acc[2][8][4];
#pragma unroll
    for (int a = 0; a < 2; a++)
#pragma unroll
        for (int b = 0; b < 8; b++)
#pragma unroll
            for (int c = 0; c < 4; c++) acc[a][b][c] = 0.f;

    gemm_core(g_xhi, g_xlo, g_whi, g_wlo, row0, col0, Ee, sm, acc);

    const int sel = col0 >> 11;          // 0=Q 1=K 2=V
    const int nc0 = col0 & 2047;
#pragma unroll
    for (int mi = 0; mi < 2; mi++)
#pragma unroll
        for (int nj = 0; nj < 8; nj++) {
            int r = row0 + wm + mi * 16 + (lane >> 2);
            int c = nc0 + wn + nj * 8 + (lane & 3) * 2;
            if (sel == 0) {
                *(float2*)&g_qraw[(size_t)r * Ee + c] = make_float2(acc[mi][nj][0], acc[mi][nj][1]);
                *(float2*)&g_qraw[(size_t)(r + 8) * Ee + c] = make_float2(acc[mi][nj][2], acc[mi][nj][3]);
            } else if (sel == 1) {
                *(float2*)&g_kraw[(size_t)r * Ee + c] = make_float2(acc[mi][nj][0], acc[mi][nj][1]);
                *(float2*)&g_kraw[(size_t)(r + 8) * Ee + c] = make_float2(acc[mi][nj][2], acc[mi][nj][3]);
            } else {
                store_hl(g_vhib, g_vlob, (size_t)r * Ee + c, acc[mi][nj][0], acc[mi][nj][1]);
                store_hl(g_vhib, g_vlob, (size_t)(r + 8) * Ee + c, acc[mi][nj][2], acc[mi][nj][3]);
            }
        }
}

// output projection: y @ wo^T -> out (fp32)
__global__ __launch_bounds__(256, 2) void gemm_out(float* __restrict__ C) {
    extern __shared__ __align__(16) __nv_bfloat16 sm[];
    const int row0 = blockIdx.y * BM, col0 = blockIdx.x * BN;
    const int lane = threadIdx.x & 31, warp = threadIdx.x >> 5;
    const int wm = (warp & 3) * 32, wn = (warp >> 2) * 64;

    float acc[2][8][4];
#pragma unroll
    for (int a = 0; a < 2; a++)
#pragma unroll
        for (int b = 0; b < 8; b++)
#pragma unroll
            for (int c = 0; c < 4; c++) acc[a][b][c] = 0.f;

    const size_t WSZ = (size_t)Ee * Ee;
    gemm_core(g_yhi, g_ylo, g_whi + 3 * WSZ, g_wlo + 3 * WSZ, row0, col0, Ee, sm, acc);

#pragma unroll
    for (int mi = 0; mi < 2; mi++)
#pragma unroll
        for (int nj = 0; nj < 8; nj++) {
            int r = row0 + wm + mi * 16 + (lane >> 2);
            int c = col0 + wn + nj * 8 + (lane & 3) * 2;
            *(float2*)&C[(size_t)r * Ee + c] = make_float2(acc[mi][nj][0], acc[mi][nj][1]);
            *(float2*)&C[(size_t)(r + 8) * Ee + c] = make_float2(acc[mi][nj][2], acc[mi][nj][3]);
        }
}

// ------------------------ lambda scalar ------------------------
__global__ void lam_kernel(const float* __restrict__ lq1, const float* __restrict__ lq2,
                           const float* __restrict__ lk1, const float* __restrict__ lk2) {
    __shared__ float s1[64], s2[64];
    int t = threadIdx.x;
    s1[t] = lq1[t] * lk1[t];
    s2[t] = lq2[t] * lk2[t];
    __syncthreads();
    for (int s = 32; s > 0; s >>= 1) {
        if (t < s) { s1[t] += s1[t + s]; s2[t] += s2[t + s]; }
        __syncthreads();
    }
    if (t == 0) g_lam[0] = expf(s1[0]) - expf(s2[0]) + LAMBDA_INIT;
}

// ------------------------ RoPE cos/sin table ------------------------
__global__ void rope_table() {
    int idx = blockIdx.x * blockDim.x + threadIdx.x;
    if (idx >= Tt * 32) return;
    int t = idx / 32, i = idx % 32;
    float invf = (float)exp(-((double)i / 32.0) * log(10000.0));
    float ang = (float)t * invf;
    g_cos[idx] = cosf(ang);
    g_sin[idx] = sinf(ang);
}

// ------------------------ rope q+k (merged) -> (B,2H,T,D) bf16 hi/lo ------------------------
__global__ void rope_qk_kernel(const float* __restrict__ rel_pos) {
    int idx = blockIdx.x * blockDim.x + threadIdx.x;
    const int np = Bb * Tt * H2 * 32;
    if (idx >= 2 * np) return;
    const bool isq = idx < np;
    if (!isq) idx -= np;
    int i = idx & 31;
    int hh = (idx >> 5) & (H2 - 1);
    int t = (idx >> 10) & (Tt - 1);
    int b = idx >> 20;
    size_t in = (size_t)(b * Tt + t) * Ee + hh * Dd + 2 * i;
    float x1, x2;
    if (isq) { x1 = g_qraw[in]; x2 = g_qraw[in + 1]; }
    else {
        x1 = g_kraw[in] * rel_pos[t * Dd + 2 * i];
        x2 = g_kraw[in + 1] * rel_pos[t * Dd + 2 * i + 1];
    }
    float c = g_cos[t * 32 + i], s = g_sin[t * 32 + i];
    float r1 = x1 * c - x2 * s;
    float r2 = x1 * s + x2 * c;
    size_t out = ((size_t)(b * H2 + hh) * Tt + t) * Dd + 2 * i;
    __nv_bfloat16 h1 = __float2bfloat16(r1), h2 = __float2bfloat16(r2);
    __nv_bfloat16 l1 = __float2bfloat16(r1 - __bfloat162float(h1));
    __nv_bfloat16 l2 = __float2bfloat16(r2 - __bfloat162float(h2));
    if (isq) {
        g_qhib[out] = h1; g_qhib[out + 1] = h2;
        g_qlob[out] = l1; g_qlob[out + 1] = l2;
    } else {
        g_khib[out] = h1; g_khib[out + 1] = h2;
        g_klob[out] = l1; g_klob[out + 1] = l2;
    }
}

// ------------------------ fused flash differential attention ------------------------
// single-buffer K/V (2 CTAs/SM); K reloaded after score-phase barrier, V after tile barrier.
// smem elems: Qh 4608 | Ql 4608 | Kh 4608 | Kl 4608 | Vh 8704 | Vl 8704 | Ph 4608 | Pl 4608
#define FA_SMEM_ELE 45056
#define FA_SMEM_BYTES (FA_SMEM_ELE*2 + 448*4)

__global__ __launch_bounds__(256, 2) void fattn_kernel() {
    extern __shared__ __align__(16) __nv_bfloat16 fsm[];
    __nv_bfloat16* sQh = fsm;
    __nv_bfloat16* sQl = fsm + 4608;
    __nv_bfloat16* sKh = fsm + 9216;
    __nv_bfloat16* sKl = fsm + 13824;
    __nv_bfloat16* sVh = fsm + 18432;
    __nv_bfloat16* sVl = fsm + 27136;
    __nv_bfloat16* sPh = fsm + 35840;
    __nv_bfloat16* sPl = fsm + 40448;
    float* fst   = (float*)(fsm + FA_SMEM_ELE);
    float* sm_m  = fst;          // [64]
    float* sm_l  = fst + 64;
    float* sm_al = fst + 128;
    float* rmax  = fst + 192;    // [2][64]
    float* rsum  = fst + 320;    // [2][64]

    const int tid = threadIdx.x, lane = tid & 31, warp = tid >> 5;
    const int comp = blockIdx.y;
    const int b = comp >> 5;
    const int hh = comp & 31;
    const int qt = (int)gridDim.x - 1 - (int)blockIdx.x;   // heavy blocks first
    const int q0 = qt * 64;

    const __nv_bfloat16* qh = g_qhib + ((size_t)comp * Tt + q0) * Dd;
    const __nv_bfloat16* ql = g_qlob + ((size_t)comp * Tt + q0) * Dd;
    const __nv_bfloat16* kh = g_khib + (size_t)comp * Tt * Dd;
    const __nv_bfloat16* kl = g_klob + (size_t)comp * Tt * Dd;
    const __nv_bfloat16* vh = g_vhib + (size_t)b * Tt * Ee + (hh >> 1) * D2;
    const __nv_bfloat16* vl = g_vlob + (size_t)b * Tt * Ee + (hh >> 1) * D2;

    if (tid < 64) { sm_m[tid] = -1e30f; sm_l[tid] = 0.f; }

    auto load_k = [&](int jt) {
        const __nv_bfloat16* gkh = kh + (size_t)(jt * 64) * Dd;
        const __nv_bfloat16* gkl = kl + (size_t)(jt * 64) * Dd;
#pragma unroll
        for (int i = 0; i < 2; i++) {
            int ch = tid + i * 256, r = ch >> 3, c = (ch & 7) * 8;
            cp16(s2u(sKh + r * 72 + c), gkh + (size_t)r * Dd + c);
            cp16(s2u(sKl + r * 72 + c), gkl + (size_t)r * Dd + c);
        }
    };
    auto load_v = [&](int jt) {
        const __nv_bfloat16* gvh = vh + (size_t)(jt * 64) * Ee;
        const __nv_bfloat16* gvl = vl + (size_t)(jt * 64) * Ee;
#pragma unroll
        for (int i = 0; i < 4; i++) {
            int ch = tid + i * 256, r = ch >> 4, c = (ch & 15) * 8;
            cp16(s2u(sVh + r * 136 + c), gvh + (size_t)r * Ee + c);
            cp16(s2u(sVl + r * 136 + c), gvl + (size_t)r * Ee + c);
        }
    };

    // prologue: Q + K0 + V0 in one group
    {
#pragma unroll
        for (int i = 0; i < 2; i++) {
            int ch = tid + i * 256, r = ch >> 3, c = (ch & 7) * 8;
            cp16(s2u(sQh + r * 72 + c), qh + (size_t)r * Dd + c);
            cp16(s2u(sQl + r * 72 + c), ql + (size_t)r * Dd + c);
        }
        load_k(0);
        load_v(0);
        CP_COMMIT();
    }

    float O[2][4][4];
#pragma unroll
    for (int a = 0; a < 2; a++)
#pragma unroll
        for (int c = 0; c < 4; c++)
#pragma unroll
            for (int e = 0; e < 4; e++) O[a][c][e] = 0.f;

    const int wm = warp & 3, wn = warp >> 2;     // score view: m16 x n32
    const int wm2 = warp & 1, wn2 = warp >> 1;   // pv view:    m32 x n32
    const int njt = qt + 1;

    for (int jt = 0; jt < njt; jt++) {
        CP_WAIT0();
        __syncthreads();

        // ---- scores S = Q K^T (bf16x3)
        float S[4][4];
#pragma unroll
        for (int nf = 0; nf < 4; nf++)
#pragma unroll
            for (int e = 0; e < 4; e++) S[nf][e] = 0.f;
        {
            const int arow = wm * 16 + (lane & 7) + ((lane >> 3) & 1) * 8;
            const int brow = (lane >> 4) * 8 + (lane & 7);
#pragma unroll
            for (int ks = 0; ks < 4; ks++) {
                unsigned ah[4], al[4], bh0[4], bh1[4], bl0[4], bl1[4];
                int acol = ks * 16 + (lane >> 4) * 8;
                LDSM4(ah, s2u(sQh + arow * 72 + acol));
                LDSM4(al, s2u(sQl + arow * 72 + acol));
                int bcol = ks * 16 + ((lane >> 3) & 1) * 8;
                LDSM4(bh0, s2u(sKh + (wn * 32 + brow) * 72 + bcol));
                LDSM4(bh1, s2u(sKh + (wn * 32 + 16 + brow) * 72 + bcol));
                LDSM4(bl0, s2u(sKl + (wn * 32 + brow) * 72 + bcol));
                LDSM4(bl1, s2u(sKl + (wn * 32 + 16 + brow) * 72 + bcol));
#pragma unroll
                for (int nf = 0; nf < 4; nf++) {
                    const unsigned* bh = (nf < 2 ? bh0 : bh1) + (nf & 1) * 2;
                    const unsigned* bl = (nf < 2 ? bl0 : bl1) + (nf & 1) * 2;
                    MMA_BF16(S[nf], ah, bh);
                    MMA_BF16(S[nf], ah, bl);
                    MMA_BF16(S[nf], al, bh);
                }
            }
        }
        // ---- scale + causal mask
        const bool diag = (jt == qt);
        const int rl0 = wm * 16 + (lane >> 2);
#pragma unroll
        for (int nf = 0; nf < 4; nf++) {
            int cl = wn * 32 + nf * 8 + (lane & 3) * 2;
#pragma unroll
            for (int hn = 0; hn < 2; hn++)
#pragma unroll
                for (int e = 0; e < 2; e++) {
                    float s = S[nf][hn * 2 + e] * 0.125f;
                    if (diag && (cl + e > rl0 + hn * 8)) s = -1e30f;
                    S[nf][hn * 2 + e] = s;
                }
        }
        // ---- row max (partial within warp cols)
        {
            float mx0 = -1e30f, mx1 = -1e30f;
#pragma unroll
            for (int nf = 0; nf < 4; nf++) {
                mx0 = fmaxf(mx0, fmaxf(S[nf][0], S[nf][1]));
                mx1 = fmaxf(mx1, fmaxf(S[nf][2], S[nf][3]));
            }
            mx0 = fmaxf(mx0, __shfl_xor_sync(0xFFFFFFFFu, mx0, 1));
            mx0 = fmaxf(mx0, __shfl_xor_sync(0xFFFFFFFFu, mx0, 2));
            mx1 = fmaxf(mx1, __shfl_xor_sync(0xFFFFFFFFu, mx1, 1));
            mx1 = fmaxf(mx1, __shfl_xor_sync(0xFFFFFFFFu, mx1, 2));
            if ((lane & 3) == 0) {
                rmax[wn * 64 + rl0] = mx0;
                rmax[wn * 64 + rl0 + 8] = mx1;
            }
        }
        __syncthreads();   // A: all K reads + rmax writes done
        if (jt + 1 < njt) { load_k(jt + 1); CP_COMMIT(); }   // K reload overlaps softmax+PV
        if (tid < 64) {
            float mo = sm_m[tid];
            float mn = fmaxf(mo, fmaxf(rmax[tid], rmax[64 + tid]));
            sm_m[tid] = mn;
            sm_al[tid] = __expf(mo - mn);
        }
        __syncthreads();   // B
        // ---- p = exp(S - m), row sums, store P hi/lo to smem
        {
            float mrow0 = sm_m[rl0], mrow1 = sm_m[rl0 + 8];
            float s0 = 0.f, s1 = 0.f;
#pragma unroll
            for (int nf = 0; nf < 4; nf++) {
                int cl = wn * 32 + nf * 8 + (lane & 3) * 2;
                float p00 = __expf(S[nf][0] - mrow0);
                float p01 = __expf(S[nf][1] - mrow0);
                float p10 = __expf(S[nf][2] - mrow1);
                float p11 = __expf(S[nf][3] - mrow1);
                s0 += p00 + p01; s1 += p10 + p11;
                float h00 = __bfloat162float(__float2bfloat16(p00));
                float h01 = __bfloat162float(__float2bfloat16(p01));
                float h10 = __bfloat162float(__float2bfloat16(p10));
                float h11 = __bfloat162float(__float2bfloat16(p11));
                *(unsigned*)(sPh + rl0 * 72 + cl)       = packbf(h00, h01);
                *(unsigned*)(sPh + (rl0 + 8) * 72 + cl) = packbf(h10, h11);
                *(unsigned*)(sPl + rl0 * 72 + cl)       = packbf(p00 - h00, p01 - h01);
                *(unsigned*)(sPl + (rl0 + 8) * 72 + cl) = packbf(p10 - h10, p11 - h11);
            }
            s0 += __shfl_xor_sync(0xFFFFFFFFu, s0, 1);
            s0 += __shfl_xor_sync(0xFFFFFFFFu, s0, 2);
            s1 += __shfl_xor_sync(0xFFFFFFFFu, s1, 1);
            s1 += __shfl_xor_sync(0xFFFFFFFFu, s1, 2);
            if ((lane & 3) == 0) {
                rsum[wn * 64 + rl0] = s0;
                rsum[wn * 64 + rl0 + 8] = s1;
            }
        }
        __syncthreads();   // C
        if (tid < 64) sm_l[tid] = sm_l[tid] * sm_al[tid] + rsum[tid] + rsum[64 + tid];
        // ---- rescale O
        {
            const int orow = wm2 * 32 + (lane >> 2);
#pragma unroll
            for (int mf = 0; mf < 2; mf++) {
                float a0 = sm_al[orow + mf * 16];
                float a1 = sm_al[orow + mf * 16 + 8];
#pragma unroll
                for (int nf = 0; nf < 4; nf++) {
                    O[mf][nf][0] *= a0; O[mf][nf][1] *= a0;
                    O[mf][nf][2] *= a1; O[mf][nf][3] *= a1;
                }
            }
        }
        // ---- O += P V (bf16x3), V^T via ldmatrix.trans
        {
            const int prow0 = wm2 * 32 + (lane & 7) + ((lane >> 3) & 1) * 8;
            const int vcol = wn2 * 32 + (lane >> 4) * 8;
#pragma unroll
            for (int ks = 0; ks < 4; ks++) {
                unsigned pah[2][4], pal[2][4], vh0[4], vh1[4], vl0[4], vl1[4];
                int pcol = ks * 16 + (lane >> 4) * 8;
#pragma unroll
                for (int mf = 0; mf < 2; mf++) {
                    LDSM4(pah[mf], s2u(sPh + (prow0 + mf * 16) * 72 + pcol));
                    LDSM4(pal[mf], s2u(sPl + (prow0 + mf * 16) * 72 + pcol));
                }
                int vrow = ks * 16 + ((lane >> 3) & 1) * 8 + (lane & 7);
                LDSM4T(vh0, s2u(sVh + vrow * 136 + vcol));
                LDSM4T(vh1, s2u(sVh + vrow * 136 + vcol + 16));
                LDSM4T(vl0, s2u(sVl + vrow * 136 + vcol));
                LDSM4T(vl1, s2u(sVl + vrow * 136 + vcol + 16));
#pragma unroll
                for (int mf = 0; mf < 2; mf++)
#pragma unroll
                    for (int nf = 0; nf < 4; nf++) {
                        const unsigned* bh = (nf < 2 ? vh0 : vh1) + (nf & 1) * 2;
                        const unsigned* bl = (nf < 2 ? vl0 : vl1) + (nf & 1) * 2;
                        MMA_BF16(O[mf][nf], pah[mf], bh);
                        MMA_BF16(O[mf][nf], pah[mf], bl);
                        MMA_BF16(O[mf][nf], pal[mf], bh);
                    }
            }
        }
        __syncthreads();   // D: all V/P reads done
        if (jt + 1 < njt) { load_v(jt + 1); CP_COMMIT(); }   // V reload
    }

    // ---- epilogue: O / l -> g_oc (comp, t, 128)
    {
        const int orow = wm2 * 32 + (lane >> 2);
#pragma unroll
        for (int mf = 0; mf < 2; mf++) {
            int r0 = orow + mf * 16, r1 = r0 + 8;
            float li0 = 1.f / sm_l[r0];
            float li1 = 1.f / sm_l[r1];
#pragma unroll
            for (int nf = 0; nf < 4; nf++) {
                int col = wn2 * 32 + nf * 8 + (lane & 3) * 2;
                *(float2*)&g_oc[((size_t)comp * Tt + q0 + r0) * D2 + col] =
                    make_float2(O[mf][nf][0] * li0, O[mf][nf][1] * li0);
                *(float2*)&g_oc[((size_t)comp * Tt + q0 + r1) * D2 + col] =
                    make_float2(O[mf][nf][2] * li1, O[mf][nf][3] * li1);
            }
        }
    }
}

// ------------------------ combine + RMS norm + subln -> bf16 hi/lo y ------------------------
__global__ __launch_bounds__(256) void rms2_kernel(const float* __restrict__ subln) {
    const int warp = threadIdx.x >> 5, lane = threadIdx.x & 31;
    const size_t row = (size_t)blockIdx.x * 8 + warp;   // over B*H*T
    int t = (int)(row & (Tt - 1));
    int h = (int)((row >> 10) & (Hh - 1));
    int b = (int)(row >> 14);
    const float lam = g_lam[0];
    const float* o0 = g_oc + ((size_t)(b * H2 + 2 * h) * Tt + t) * D2 + lane * 4;
    const float* o1 = o0 + (size_t)Tt * D2;
    float4 u = *(const float4*)o0;
    float4 w1 = *(const float4*)o1;
    float4 a;
    a.x = u.x - lam * w1.x; a.y = u.y - lam * w1.y;
    a.z = u.z - lam * w1.z; a.w = u.w - lam * w1.w;
    float ss = a.x * a.x + a.y * a.y + a.z * a.z + a.w * a.w;
#pragma unroll
    for (int o = 16; o > 0; o >>= 1) ss += __shfl_xor_sync(0xFFFFFFFFu, ss, o);
    float r = rsqrtf(ss * (1.f / 128.f) + EPS_RMS);
    const float4 w = *(const float4*)(subln + lane * 4);
    float y0 = a.x * r * w.x, y1 = a.y * r * w.y;
    float y2 = a.z * r * w.z, y3 = a.w * r * w.w;
    size_t off = (size_t)(b * Tt + t) * Ee + h * D2 + lane * 4;
    store_hl(g_yhi, g_ylo, off, y0, y1);
    store_hl(g_yhi, g_ylo, off + 2, y2, y3);
}

// ------------------------ launch ------------------------
extern "C" void kernel_launch(void* const* d_in, const int* in_sizes, int n_in,
                              void* d_out, int out_size) {
    const float* x       = (const float*)d_in[0];
    const float* rel_pos = (const float*)d_in[1];
    const float* wq      = (const float*)d_in[2];
    const float* wk      = (const float*)d_in[3];
    const float* wv      = (const float*)d_in[4];
    const float* lq1     = (const float*)d_in[5];
    const float* lq2     = (const float*)d_in[6];
    const float* lk1     = (const float*)d_in[7];
    const float* lk2     = (const float*)d_in[8];
    const float* subln   = (const float*)d_in[9];
    const float* wo      = (const float*)d_in[10];
    float* out = (float*)d_out;

    __nv_bfloat16 *xhi, *xlo, *whi, *wlo;
    cudaGetSymbolAddress((void**)&xhi, g_xhi);
    cudaGetSymbolAddress((void**)&xlo, g_xlo);
    cudaGetSymbolAddress((void**)&whi, g_whi);
    cudaGetSymbolAddress((void**)&wlo, g_wlo);

    cudaFuncSetAttribute(gemm_qkv, cudaFuncAttributeMaxDynamicSharedMemorySize, GSMEM);
    cudaFuncSetAttribute(gemm_out, cudaFuncAttributeMaxDynamicSharedMemorySize, GSMEM);
    cudaFuncSetAttribute(fattn_kernel, cudaFuncAttributeMaxDynamicSharedMemorySize, FA_SMEM_BYTES);

    const int n4 = Mm * Ee / 4;

    // position 4 = fused QKV gemm (ncu -s window captures launch #4)
    cvt_split<<<(n4 + 255) / 256, 256>>>(x, xhi, xlo, n4);                   // 1
    cvt_split4<<<(4 * n4 + 255) / 256, 256>>>(wq, wk, wv, wo, whi, wlo);     // 2
    rope_table<<<(Tt * 32 + 255) / 256, 256>>>();                            // 3
    gemm_qkv<<<dim3(3 * Ee / BN, Mm / BM), 256, GSMEM>>>();                  // 4
    lam_kernel<<<1, 64>>>(lq1, lq2, lk1, lk2);                               // 5

    int np2 = 2 * Bb * Tt * H2 * 32;
    rope_qk_kernel<<<(np2 + 255) / 256, 256>>>(rel_pos);

    fattn_kernel<<<dim3(Tt / 64, Bb * H2), 256, FA_SMEM_BYTES>>>();
    rms2_kernel<<<Bb * Hh * Tt / 8, 256>>>(subln);

    gemm_out<<<dim3(Ee / BN, Mm / BM), 256, GSMEM>>>(out);
}

// round 15
// speedup vs baseline: 1.0931x; 1.0931x over previous
#include <cuda_runtime.h>
#include <cuda_bf16.h>
#include <math.h>
#include <stdint.h>

// Problem constants
#define Bb 2
#define Tt 1024
#define Ee 2048
#define Hh 16
#define Dd 64
#define H2 32          // 2*H
#define D2 128         // 2*D
#define Mm (Bb*Tt)     // 2048
#define LAMBDA_INIT 0.78360576653162f
#define EPS_RMS 1e-5f

// ------------------------ scratch (static device memory) ------------------------
__device__ float g_qraw[(size_t)Mm*Ee];
__device__ float g_kraw[(size_t)Mm*Ee];
__device__ float g_oc[(size_t)Bb*H2*Tt*D2];   // per-component attention output
__device__ float g_lam[1];
__device__ float g_cos[Tt*32];
__device__ float g_sin[Tt*32];

// bf16 split buffers
__device__ __nv_bfloat16 g_xhi[(size_t)Mm*Ee];
__device__ __nv_bfloat16 g_xlo[(size_t)Mm*Ee];
__device__ __nv_bfloat16 g_whi[(size_t)4*Ee*Ee];
__device__ __nv_bfloat16 g_wlo[(size_t)4*Ee*Ee];
__device__ __nv_bfloat16 g_yhi[(size_t)Mm*Ee];
__device__ __nv_bfloat16 g_ylo[(size_t)Mm*Ee];
// rope'd q/k in (B,2H,T,D), hi/lo split
__device__ __nv_bfloat16 g_qhib[(size_t)Bb*H2*Tt*Dd];
__device__ __nv_bfloat16 g_qlob[(size_t)Bb*H2*Tt*Dd];
__device__ __nv_bfloat16 g_khib[(size_t)Bb*H2*Tt*Dd];
__device__ __nv_bfloat16 g_klob[(size_t)Bb*H2*Tt*Dd];
// v split in (b,t,e) -- written directly by the QKV GEMM epilogue
__device__ __nv_bfloat16 g_vhib[(size_t)Mm*Ee];
__device__ __nv_bfloat16 g_vlob[(size_t)Mm*Ee];

// ------------------------ helpers ------------------------
__device__ __forceinline__ unsigned s2u(const void* p) {
    return (unsigned)__cvta_generic_to_shared(p);
}
__device__ __forceinline__ void cp16(unsigned saddr, const void* g) {
    asm volatile("cp.async.cg.shared.global [%0], [%1], 16;\n" :: "r"(saddr), "l"(g));
}
#define CP_COMMIT() asm volatile("cp.async.commit_group;\n" ::: "memory")
#define CP_WAIT0()  asm volatile("cp.async.wait_group 0;\n" ::: "memory")
#define CP_WAIT1()  asm volatile("cp.async.wait_group 1;\n" ::: "memory")

#define LDSM4(r, addr) \
    asm volatile("ldmatrix.sync.aligned.m8n8.x4.shared.b16 {%0,%1,%2,%3}, [%4];" \
        : "=r"((r)[0]), "=r"((r)[1]), "=r"((r)[2]), "=r"((r)[3]) : "r"(addr))
#define LDSM4T(r, addr) \
    asm volatile("ldmatrix.sync.aligned.m8n8.x4.trans.shared.b16 {%0,%1,%2,%3}, [%4];" \
        : "=r"((r)[0]), "=r"((r)[1]), "=r"((r)[2]), "=r"((r)[3]) : "r"(addr))

#define MMA_BF16(d, a, b) \
    asm volatile("mma.sync.aligned.m16n8k16.row.col.f32.bf16.bf16.f32 " \
        "{%0,%1,%2,%3}, {%4,%5,%6,%7}, {%8,%9}, {%0,%1,%2,%3};" \
        : "+f"((d)[0]), "+f"((d)[1]), "+f"((d)[2]), "+f"((d)[3]) \
        : "r"((a)[0]), "r"((a)[1]), "r"((a)[2]), "r"((a)[3]), "r"((b)[0]), "r"((b)[1]))

__device__ __forceinline__ unsigned packbf(float a, float b) {
    unsigned short ua = __bfloat16_as_ushort(__float2bfloat16(a));
    unsigned short ub = __bfloat16_as_ushort(__float2bfloat16(b));
    return (unsigned)ua | ((unsigned)ub << 16);
}
// hi/lo split of a pair, packed as 2x bf16 words
__device__ __forceinline__ void store_hl(__nv_bfloat16* hi, __nv_bfloat16* lo,
                                         size_t off, float a, float b) {
    __nv_bfloat16 ha = __float2bfloat16(a), hb = __float2bfloat16(b);
    unsigned hw = (unsigned)__bfloat16_as_ushort(ha) |
                  ((unsigned)__bfloat16_as_ushort(hb) << 16);
    unsigned lw = packbf(a - __bfloat162float(ha), b - __bfloat162float(hb));
    *(unsigned*)(hi + off) = hw;
    *(unsigned*)(lo + off) = lw;
}

// ------------------------ fp32 -> bf16 hi/lo split ------------------------
__device__ __forceinline__ void split4(const float* __restrict__ s,
                                       __nv_bfloat16* __restrict__ hi,
                                       __nv_bfloat16* __restrict__ lo, int i) {
    float4 v = ((const float4*)s)[i];
    __nv_bfloat16 h0 = __float2bfloat16(v.x);
    __nv_bfloat16 h1 = __float2bfloat16(v.y);
    __nv_bfloat16 h2 = __float2bfloat16(v.z);
    __nv_bfloat16 h3 = __float2bfloat16(v.w);
    __nv_bfloat16 l0 = __float2bfloat16(v.x - __bfloat162float(h0));
    __nv_bfloat16 l1 = __float2bfloat16(v.y - __bfloat162float(h1));
    __nv_bfloat16 l2 = __float2bfloat16(v.z - __bfloat162float(h2));
    __nv_bfloat16 l3 = __float2bfloat16(v.w - __bfloat162float(h3));
    ushort4 hv, lv;
    hv.x = __bfloat16_as_ushort(h0); hv.y = __bfloat16_as_ushort(h1);
    hv.z = __bfloat16_as_ushort(h2); hv.w = __bfloat16_as_ushort(h3);
    lv.x = __bfloat16_as_ushort(l0); lv.y = __bfloat16_as_ushort(l1);
    lv.z = __bfloat16_as_ushort(l2); lv.w = __bfloat16_as_ushort(l3);
    ((ushort4*)hi)[i] = hv;
    ((ushort4*)lo)[i] = lv;
}

__global__ __launch_bounds__(256) void cvt_split(const float* __restrict__ s,
                                                 __nv_bfloat16* __restrict__ hi,
                                                 __nv_bfloat16* __restrict__ lo, int n4) {
    int i = blockIdx.x * blockDim.x + threadIdx.x;
    if (i >= n4) return;
    split4(s, hi, lo, i);
}

// all 4 weight matrices in one launch; each is exactly 2^20 float4s
__global__ __launch_bounds__(256) void cvt_split4(
    const float* __restrict__ w0, const float* __restrict__ w1,
    const float* __restrict__ w2, const float* __restrict__ w3,
    __nv_bfloat16* __restrict__ hi, __nv_bfloat16* __restrict__ lo) {
    int idx = blockIdx.x * blockDim.x + threadIdx.x;   // 0 .. 4*2^20-1
    int sel = idx >> 20;
    int i = idx & ((1 << 20) - 1);
    const float* w = (sel == 0) ? w0 : (sel == 1) ? w1 : (sel == 2) ? w2 : w3;
    size_t off = (size_t)sel << 22;                    // sel * Ee*Ee elems
    split4(w, hi + off, lo + off, i);
}

// ------------------------ bf16x3 GEMM core: acc += A[M,K] @ B[N,K]^T tile ------------------------
// BM=BN=128, BK=32(bf16), 256 threads (8 warps 4x2), 2-stage cp.async, 2 CTAs/SM.
// R11 measured-best pipeline: CP_WAIT1 depth-1, frag load -> mid-tile sync at kk=1 -> issue.
#define BM 128
#define BN 128
#define BKg 32
#define KP 40                    // padded bf16 row stride (80B): conflict-free ldmatrix
#define STG (4*128*KP)           // elems per stage: Ahi,Alo,Bhi,Blo
#define GSMEM (2*STG*2)          // 81920 B

__device__ __forceinline__ void gemm_core(
    const __nv_bfloat16* __restrict__ Ahi, const __nv_bfloat16* __restrict__ Alo,
    const __nv_bfloat16* __restrict__ Bhi, const __nv_bfloat16* __restrict__ Blo,
    int row0, int col0, int K,
    __nv_bfloat16* sm, float acc[2][8][4])
{
    const int tid = threadIdx.x;
    const int lane = tid & 31, warp = tid >> 5;
    const int wm = (warp & 3) * 32, wn = (warp >> 2) * 64;
    const int lr = tid >> 2, lq = (tid & 3) * 8;

    const __nv_bfloat16* gbase[4] = {Ahi, Alo, Bhi, Blo};
    const int grow0[4] = {row0, row0, col0, col0};

    auto issue = [&](int buf, int k0) {
        __nv_bfloat16* s = sm + buf * STG;
#pragma unroll
        for (int a = 0; a < 4; a++) {
            const __nv_bfloat16* g = gbase[a] + (size_t)(grow0[a] + lr) * K + k0 + lq;
            cp16(s2u(s + a * 128 * KP + lr * KP + lq), g);
            cp16(s2u(s + a * 128 * KP + (lr + 64) * KP + lq), g + (size_t)64 * K);
        }
        CP_COMMIT();
    };

    issue(0, 0);
    issue(1, BKg);

    const int niter = K / BKg;
    for (int it = 0; it < niter; it++) {
        if (it + 1 < niter) CP_WAIT1(); else CP_WAIT0();
        __syncthreads();                       // stage it&1 visible to all

        __nv_bfloat16* s = sm + (it & 1) * STG;
        __nv_bfloat16* sAhi = s;
        __nv_bfloat16* sAlo = s + 128 * KP;
        __nv_bfloat16* sBhi = s + 2 * 128 * KP;
        __nv_bfloat16* sBlo = s + 3 * 128 * KP;

#pragma unroll
        for (int kk = 0; kk < 2; kk++) {
            unsigned afh[2][4], afl[2][4], bfh[4][4], bfl[4][4];
#pragma unroll
            for (int mi = 0; mi < 2; mi++) {
                int r = wm + mi * 16 + (lane & 15);
                int c = kk * 16 + (lane >> 4) * 8;
                LDSM4(afh[mi], s2u(sAhi + r * KP + c));
                LDSM4(afl[mi], s2u(sAlo + r * KP + c));
            }
#pragma unroll
            for (int p = 0; p < 4; p++) {
                int r = wn + p * 16 + ((lane >> 4) & 1) * 8 + (lane & 7);
                int c = kk * 16 + ((lane >> 3) & 1) * 8;
                LDSM4(bfh[p], s2u(sBhi + r * KP + c));
                LDSM4(bfl[p], s2u(sBlo + r * KP + c));
            }
            if (kk == 1) {
                __syncthreads();               // all reads of buf it&1 done
                if (it + 2 < niter) issue(it & 1, (it + 2) * BKg);
            }
            // pass 1: Ahi * Bhi
#pragma unroll
            for (int mi = 0; mi < 2; mi++)
#pragma unroll
                for (int nj = 0; nj < 8; nj++)
                    MMA_BF16(acc[mi][nj], afh[mi], &bfh[nj >> 1][(nj & 1) * 2]);
            // pass 2: Ahi * Blo
#pragma unroll
            for (int mi = 0; mi < 2; mi++)
#pragma unroll
                for (int nj = 0; nj < 8; nj++)
                    MMA_BF16(acc[mi][nj], afh[mi], &bfl[nj >> 1][(nj & 1) * 2]);
            // pass 3: Alo * Bhi
#pragma unroll
            for (int mi = 0; mi < 2; mi++)
#pragma unroll
                for (int nj = 0; nj < 8; nj++)
                    MMA_BF16(acc[mi][nj], afl[mi], &bfh[nj >> 1][(nj & 1) * 2]);
        }
    }
}

// fused QKV projection: N = 3*2048 over [wq; wk; wv] rows of g_whi
__global__ __launch_bounds__(256, 2) void gemm_qkv() {
    extern __shared__ __align__(16) __nv_bfloat16 sm[];
    const int row0 = blockIdx.y * BM, col0 = blockIdx.x * BN;
    const int lane = threadIdx.x & 31, warp = threadIdx.x >> 5;
    const int wm = (warp & 3) * 32, wn = (warp >> 2) * 64;

    float acc[2][8][4];
#pragma unroll
    for (int a = 0; a < 2; a++)
#pragma unroll
        for (int b = 0; b < 8; b++)
#pragma unroll
            for (int c = 0; c < 4; c++) acc[a][b][c] = 0.f;

    gemm_core(g_xhi, g_xlo, g_whi, g_wlo, row0, col0, Ee, sm, acc);

    const int sel = col0 >> 11;          // 0=Q 1=K 2=V
    const int nc0 = col0 & 2047;
#pragma unroll
    for (int mi = 0; mi < 2; mi++)
#pragma unroll
        for (int nj = 0; nj < 8; nj++) {
            int r = row0 + wm + mi * 16 + (lane >> 2);
            int c = nc0 + wn + nj * 8 + (lane & 3) * 2;
            if (sel == 0) {
                *(float2*)&g_qraw[(size_t)r * Ee + c] = make_float2(acc[mi][nj][0], acc[mi][nj][1]);
                *(float2*)&g_qraw[(size_t)(r + 8) * Ee + c] = make_float2(acc[mi][nj][2], acc[mi][nj][3]);
            } else if (sel == 1) {
                *(float2*)&g_kraw[(size_t)r * Ee + c] = make_float2(acc[mi][nj][0], acc[mi][nj][1]);
                *(float2*)&g_kraw[(size_t)(r + 8) * Ee + c] = make_float2(acc[mi][nj][2], acc[mi][nj][3]);
            } else {
                store_hl(g_vhib, g_vlob, (size_t)r * Ee + c, acc[mi][nj][0], acc[mi][nj][1]);
                store_hl(g_vhib, g_vlob, (size_t)(r + 8) * Ee + c, acc[mi][nj][2], acc[mi][nj][3]);
            }
        }
}

// output projection: y @ wo^T -> out (fp32)
__global__ __launch_bounds__(256, 2) void gemm_out(float* __restrict__ C) {
    extern __shared__ __align__(16) __nv_bfloat16 sm[];
    const int row0 = blockIdx.y * BM, col0 = blockIdx.x * BN;
    const int lane = threadIdx.x & 31, warp = threadIdx.x >> 5;
    const int wm = (warp & 3) * 32, wn = (warp >> 2) * 64;

    float acc[2][8][4];
#pragma unroll
    for (int a = 0; a < 2; a++)
#pragma unroll
        for (int b = 0; b < 8; b++)
#pragma unroll
            for (int c = 0; c < 4; c++) acc[a][b][c] = 0.f;

    const size_t WSZ = (size_t)Ee * Ee;
    gemm_core(g_yhi, g_ylo, g_whi + 3 * WSZ, g_wlo + 3 * WSZ, row0, col0, Ee, sm, acc);

#pragma unroll
    for (int mi = 0; mi < 2; mi++)
#pragma unroll
        for (int nj = 0; nj < 8; nj++) {
            int r = row0 + wm + mi * 16 + (lane >> 2);
            int c = col0 + wn + nj * 8 + (lane & 3) * 2;
            *(float2*)&C[(size_t)r * Ee + c] = make_float2(acc[mi][nj][0], acc[mi][nj][1]);
            *(float2*)&C[(size_t)(r + 8) * Ee + c] = make_float2(acc[mi][nj][2], acc[mi][nj][3]);
        }
}

// ------------------------ lambda scalar ------------------------
__global__ void lam_kernel(const float* __restrict__ lq1, const float* __restrict__ lq2,
                           const float* __restrict__ lk1, const float* __restrict__ lk2) {
    __shared__ float s1[64], s2[64];
    int t = threadIdx.x;
    s1[t] = lq1[t] * lk1[t];
    s2[t] = lq2[t] * lk2[t];
    __syncthreads();
    for (int s = 32; s > 0; s >>= 1) {
        if (t < s) { s1[t] += s1[t + s]; s2[t] += s2[t + s]; }
        __syncthreads();
    }
    if (t == 0) g_lam[0] = expf(s1[0]) - expf(s2[0]) + LAMBDA_INIT;
}

// ------------------------ RoPE cos/sin table ------------------------
__global__ void rope_table() {
    int idx = blockIdx.x * blockDim.x + threadIdx.x;
    if (idx >= Tt * 32) return;
    int t = idx / 32, i = idx % 32;
    float invf = (float)exp(-((double)i / 32.0) * log(10000.0));
    float ang = (float)t * invf;
    g_cos[idx] = cosf(ang);
    g_sin[idx] = sinf(ang);
}

// ------------------------ rope q+k (merged) -> (B,2H,T,D) bf16 hi/lo ------------------------
__global__ void rope_qk_kernel(const float* __restrict__ rel_pos) {
    int idx = blockIdx.x * blockDim.x + threadIdx.x;
    const int np = Bb * Tt * H2 * 32;
    if (idx >= 2 * np) return;
    const bool isq = idx < np;
    if (!isq) idx -= np;
    int i = idx & 31;
    int hh = (idx >> 5) & (H2 - 1);
    int t = (idx >> 10) & (Tt - 1);
    int b = idx >> 20;
    size_t in = (size_t)(b * Tt + t) * Ee + hh * Dd + 2 * i;
    float x1, x2;
    if (isq) { x1 = g_qraw[in]; x2 = g_qraw[in + 1]; }
    else {
        x1 = g_kraw[in] * rel_pos[t * Dd + 2 * i];
        x2 = g_kraw[in + 1] * rel_pos[t * Dd + 2 * i + 1];
    }
    float c = g_cos[t * 32 + i], s = g_sin[t * 32 + i];
    float r1 = x1 * c - x2 * s;
    float r2 = x1 * s + x2 * c;
    size_t out = ((size_t)(b * H2 + hh) * Tt + t) * Dd + 2 * i;
    __nv_bfloat16 h1 = __float2bfloat16(r1), h2 = __float2bfloat16(r2);
    __nv_bfloat16 l1 = __float2bfloat16(r1 - __bfloat162float(h1));
    __nv_bfloat16 l2 = __float2bfloat16(r2 - __bfloat162float(h2));
    if (isq) {
        g_qhib[out] = h1; g_qhib[out + 1] = h2;
        g_qlob[out] = l1; g_qlob[out + 1] = l2;
    } else {
        g_khib[out] = h1; g_khib[out + 1] = h2;
        g_klob[out] = l1; g_klob[out + 1] = l2;
    }
}

// ------------------------ fused flash differential attention ------------------------
// single-buffer K/V (2 CTAs/SM); K reloaded after score-phase barrier, V after tile barrier.
// smem elems: Qh 4608 | Ql 4608 | Kh 4608 | Kl 4608 | Vh 8704 | Vl 8704 | Ph 4608 | Pl 4608
#define FA_SMEM_ELE 45056
#define FA_SMEM_BYTES (FA_SMEM_ELE*2 + 448*4)

__global__ __launch_bounds__(256, 2) void fattn_kernel() {
    extern __shared__ __align__(16) __nv_bfloat16 fsm[];
    __nv_bfloat16* sQh = fsm;
    __nv_bfloat16* sQl = fsm + 4608;
    __nv_bfloat16* sKh = fsm + 9216;
    __nv_bfloat16* sKl = fsm + 13824;
    __nv_bfloat16* sVh = fsm + 18432;
    __nv_bfloat16* sVl = fsm + 27136;
    __nv_bfloat16* sPh = fsm + 35840;
    __nv_bfloat16* sPl = fsm + 40448;
    float* fst   = (float*)(fsm + FA_SMEM_ELE);
    float* sm_m  = fst;          // [64]
    float* sm_l  = fst + 64;
    float* sm_al = fst + 128;
    float* rmax  = fst + 192;    // [2][64]
    float* rsum  = fst + 320;    // [2][64]

    const int tid = threadIdx.x, lane = tid & 31, warp = tid >> 5;
    const int comp = blockIdx.y;
    const int b = comp >> 5;
    const int hh = comp & 31;
    const int qt = (int)gridDim.x - 1 - (int)blockIdx.x;   // heavy blocks first
    const int q0 = qt * 64;

    const __nv_bfloat16* qh = g_qhib + ((size_t)comp * Tt + q0) * Dd;
    const __nv_bfloat16* ql = g_qlob + ((size_t)comp * Tt + q0) * Dd;
    const __nv_bfloat16* kh = g_khib + (size_t)comp * Tt * Dd;
    const __nv_bfloat16* kl = g_klob + (size_t)comp * Tt * Dd;
    const __nv_bfloat16* vh = g_vhib + (size_t)b * Tt * Ee + (hh >> 1) * D2;
    const __nv_bfloat16* vl = g_vlob + (size_t)b * Tt * Ee + (hh >> 1) * D2;

    if (tid < 64) { sm_m[tid] = -1e30f; sm_l[tid] = 0.f; }

    auto load_k = [&](int jt) {
        const __nv_bfloat16* gkh = kh + (size_t)(jt * 64) * Dd;
        const __nv_bfloat16* gkl = kl + (size_t)(jt * 64) * Dd;
#pragma unroll
        for (int i = 0; i < 2; i++) {
            int ch = tid + i * 256, r = ch >> 3, c = (ch & 7) * 8;
            cp16(s2u(sKh + r * 72 + c), gkh + (size_t)r * Dd + c);
            cp16(s2u(sKl + r * 72 + c), gkl + (size_t)r * Dd + c);
        }
    };
    auto load_v = [&](int jt) {
        const __nv_bfloat16* gvh = vh + (size_t)(jt * 64) * Ee;
        const __nv_bfloat16* gvl = vl + (size_t)(jt * 64) * Ee;
#pragma unroll
        for (int i = 0; i < 4; i++) {
            int ch = tid + i * 256, r = ch >> 4, c = (ch & 15) * 8;
            cp16(s2u(sVh + r * 136 + c), gvh + (size_t)r * Ee + c);
            cp16(s2u(sVl + r * 136 + c), gvl + (size_t)r * Ee + c);
        }
    };

    // prologue: Q + K0 + V0 in one group
    {
#pragma unroll
        for (int i = 0; i < 2; i++) {
            int ch = tid + i * 256, r = ch >> 3, c = (ch & 7) * 8;
            cp16(s2u(sQh + r * 72 + c), qh + (size_t)r * Dd + c);
            cp16(s2u(sQl + r * 72 + c), ql + (size_t)r * Dd + c);
        }
        load_k(0);
        load_v(0);
        CP_COMMIT();
    }

    float O[2][4][4];
#pragma unroll
    for (int a = 0; a < 2; a++)
#pragma unroll
        for (int c = 0; c < 4; c++)
#pragma unroll
            for (int e = 0; e < 4; e++) O[a][c][e] = 0.f;

    const int wm = warp & 3, wn = warp >> 2;     // score view: m16 x n32
    const int wm2 = warp & 1, wn2 = warp >> 1;   // pv view:    m32 x n32
    const int njt = qt + 1;

    for (int jt = 0; jt < njt; jt++) {
        CP_WAIT0();
        __syncthreads();

        // ---- scores S = Q K^T (bf16x3)
        float S[4][4];
#pragma unroll
        for (int nf = 0; nf < 4; nf++)
#pragma unroll
            for (int e = 0; e < 4; e++) S[nf][e] = 0.f;
        {
            const int arow = wm * 16 + (lane & 7) + ((lane >> 3) & 1) * 8;
            const int brow = (lane >> 4) * 8 + (lane & 7);
#pragma unroll
            for (int ks = 0; ks < 4; ks++) {
                unsigned ah[4], al[4], bh0[4], bh1[4], bl0[4], bl1[4];
                int acol = ks * 16 + (lane >> 4) * 8;
                LDSM4(ah, s2u(sQh + arow * 72 + acol));
                LDSM4(al, s2u(sQl + arow * 72 + acol));
                int bcol = ks * 16 + ((lane >> 3) & 1) * 8;
                LDSM4(bh0, s2u(sKh + (wn * 32 + brow) * 72 + bcol));
                LDSM4(bh1, s2u(sKh + (wn * 32 + 16 + brow) * 72 + bcol));
                LDSM4(bl0, s2u(sKl + (wn * 32 + brow) * 72 + bcol));
                LDSM4(bl1, s2u(sKl + (wn * 32 + 16 + brow) * 72 + bcol));
#pragma unroll
                for (int nf = 0; nf < 4; nf++) {
                    const unsigned* bh = (nf < 2 ? bh0 : bh1) + (nf & 1) * 2;
                    const unsigned* bl = (nf < 2 ? bl0 : bl1) + (nf & 1) * 2;
                    MMA_BF16(S[nf], ah, bh);
                    MMA_BF16(S[nf], ah, bl);
                    MMA_BF16(S[nf], al, bh);
                }
            }
        }
        // ---- scale + causal mask
        const bool diag = (jt == qt);
        const int rl0 = wm * 16 + (lane >> 2);
#pragma unroll
        for (int nf = 0; nf < 4; nf++) {
            int cl = wn * 32 + nf * 8 + (lane & 3) * 2;
#pragma unroll
            for (int hn = 0; hn < 2; hn++)
#pragma unroll
                for (int e = 0; e < 2; e++) {
                    float s = S[nf][hn * 2 + e] * 0.125f;
                    if (diag && (cl + e > rl0 + hn * 8)) s = -1e30f;
                    S[nf][hn * 2 + e] = s;
                }
        }
        // ---- row max (partial within warp cols)
        {
            float mx0 = -1e30f, mx1 = -1e30f;
#pragma unroll
            for (int nf = 0; nf < 4; nf++) {
                mx0 = fmaxf(mx0, fmaxf(S[nf][0], S[nf][1]));
                mx1 = fmaxf(mx1, fmaxf(S[nf][2], S[nf][3]));
            }
            mx0 = fmaxf(mx0, __shfl_xor_sync(0xFFFFFFFFu, mx0, 1));
            mx0 = fmaxf(mx0, __shfl_xor_sync(0xFFFFFFFFu, mx0, 2));
            mx1 = fmaxf(mx1, __shfl_xor_sync(0xFFFFFFFFu, mx1, 1));
            mx1 = fmaxf(mx1, __shfl_xor_sync(0xFFFFFFFFu, mx1, 2));
            if ((lane & 3) == 0) {
                rmax[wn * 64 + rl0] = mx0;
                rmax[wn * 64 + rl0 + 8] = mx1;
            }
        }
        __syncthreads();   // A: all K reads + rmax writes done
        if (jt + 1 < njt) { load_k(jt + 1); CP_COMMIT(); }   // K reload overlaps softmax+PV
        if (tid < 64) {
            float mo = sm_m[tid];
            float mn = fmaxf(mo, fmaxf(rmax[tid], rmax[64 + tid]));
            sm_m[tid] = mn;
            sm_al[tid] = __expf(mo - mn);
        }
        __syncthreads();   // B
        // ---- p = exp(S - m), row sums, store P hi/lo to smem
        {
            float mrow0 = sm_m[rl0], mrow1 = sm_m[rl0 + 8];
            float s0 = 0.f, s1 = 0.f;
#pragma unroll
            for (int nf = 0; nf < 4; nf++) {
                int cl = wn * 32 + nf * 8 + (lane & 3) * 2;
                float p00 = __expf(S[nf][0] - mrow0);
                float p01 = __expf(S[nf][1] - mrow0);
                float p10 = __expf(S[nf][2] - mrow1);
                float p11 = __expf(S[nf][3] - mrow1);
                s0 += p00 + p01; s1 += p10 + p11;
                float h00 = __bfloat162float(__float2bfloat16(p00));
                float h01 = __bfloat162float(__float2bfloat16(p01));
                float h10 = __bfloat162float(__float2bfloat16(p10));
                float h11 = __bfloat162float(__float2bfloat16(p11));
                *(unsigned*)(sPh + rl0 * 72 + cl)       = packbf(h00, h01);
                *(unsigned*)(sPh + (rl0 + 8) * 72 + cl) = packbf(h10, h11);
                *(unsigned*)(sPl + rl0 * 72 + cl)       = packbf(p00 - h00, p01 - h01);
                *(unsigned*)(sPl + (rl0 + 8) * 72 + cl) = packbf(p10 - h10, p11 - h11);
            }
            s0 += __shfl_xor_sync(0xFFFFFFFFu, s0, 1);
            s0 += __shfl_xor_sync(0xFFFFFFFFu, s0, 2);
            s1 += __shfl_xor_sync(0xFFFFFFFFu, s1, 1);
            s1 += __shfl_xor_sync(0xFFFFFFFFu, s1, 2);
            if ((lane & 3) == 0) {
                rsum[wn * 64 + rl0] = s0;
                rsum[wn * 64 + rl0 + 8] = s1;
            }
        }
        __syncthreads();   // C
        if (tid < 64) sm_l[tid] = sm_l[tid] * sm_al[tid] + rsum[tid] + rsum[64 + tid];
        // ---- rescale O
        {
            const int orow = wm2 * 32 + (lane >> 2);
#pragma unroll
            for (int mf = 0; mf < 2; mf++) {
                float a0 = sm_al[orow + mf * 16];
                float a1 = sm_al[orow + mf * 16 + 8];
#pragma unroll
                for (int nf = 0; nf < 4; nf++) {
                    O[mf][nf][0] *= a0; O[mf][nf][1] *= a0;
                    O[mf][nf][2] *= a1; O[mf][nf][3] *= a1;
                }
            }
        }
        // ---- O += P V (bf16x3), V^T via ldmatrix.trans
        {
            const int prow0 = wm2 * 32 + (lane & 7) + ((lane >> 3) & 1) * 8;
            const int vcol = wn2 * 32 + (lane >> 4) * 8;
#pragma unroll
            for (int ks = 0; ks < 4; ks++) {
                unsigned pah[2][4], pal[2][4], vh0[4], vh1[4], vl0[4], vl1[4];
                int pcol = ks * 16 + (lane >> 4) * 8;
#pragma unroll
                for (int mf = 0; mf < 2; mf++) {
                    LDSM4(pah[mf], s2u(sPh + (prow0 + mf * 16) * 72 + pcol));
                    LDSM4(pal[mf], s2u(sPl + (prow0 + mf * 16) * 72 + pcol));
                }
                int vrow = ks * 16 + ((lane >> 3) & 1) * 8 + (lane & 7);
                LDSM4T(vh0, s2u(sVh + vrow * 136 + vcol));
                LDSM4T(vh1, s2u(sVh + vrow * 136 + vcol + 16));
                LDSM4T(vl0, s2u(sVl + vrow * 136 + vcol));
                LDSM4T(vl1, s2u(sVl + vrow * 136 + vcol + 16));
#pragma unroll
                for (int mf = 0; mf < 2; mf++)
#pragma unroll
                    for (int nf = 0; nf < 4; nf++) {
                        const unsigned* bh = (nf < 2 ? vh0 : vh1) + (nf & 1) * 2;
                        const unsigned* bl = (nf < 2 ? vl0 : vl1) + (nf & 1) * 2;
                        MMA_BF16(O[mf][nf], pah[mf], bh);
                        MMA_BF16(O[mf][nf], pah[mf], bl);
                        MMA_BF16(O[mf][nf], pal[mf], bh);
                    }
            }
        }
        __syncthreads();   // D: all V/P reads done
        if (jt + 1 < njt) { load_v(jt + 1); CP_COMMIT(); }   // V reload
    }

    // ---- epilogue: O / l -> g_oc (comp, t, 128)
    {
        const int orow = wm2 * 32 + (lane >> 2);
#pragma unroll
        for (int mf = 0; mf < 2; mf++) {
            int r0 = orow + mf * 16, r1 = r0 + 8;
            float li0 = 1.f / sm_l[r0];
            float li1 = 1.f / sm_l[r1];
#pragma unroll
            for (int nf = 0; nf < 4; nf++) {
                int col = wn2 * 32 + nf * 8 + (lane & 3) * 2;
                *(float2*)&g_oc[((size_t)comp * Tt + q0 + r0) * D2 + col] =
                    make_float2(O[mf][nf][0] * li0, O[mf][nf][1] * li0);
                *(float2*)&g_oc[((size_t)comp * Tt + q0 + r1) * D2 + col] =
                    make_float2(O[mf][nf][2] * li1, O[mf][nf][3] * li1);
            }
        }
    }
}

// ------------------------ combine + RMS norm + subln -> bf16 hi/lo y ------------------------
__global__ __launch_bounds__(256) void rms2_kernel(const float* __restrict__ subln) {
    const int warp = threadIdx.x >> 5, lane = threadIdx.x & 31;
    const size_t row = (size_t)blockIdx.x * 8 + warp;   // over B*H*T
    int t = (int)(row & (Tt - 1));
    int h = (int)((row >> 10) & (Hh - 1));
    int b = (int)(row >> 14);
    const float lam = g_lam[0];
    const float* o0 = g_oc + ((size_t)(b * H2 + 2 * h) * Tt + t) * D2 + lane * 4;
    const float* o1 = o0 + (size_t)Tt * D2;
    float4 u = *(const float4*)o0;
    float4 w1 = *(const float4*)o1;
    float4 a;
    a.x = u.x - lam * w1.x; a.y = u.y - lam * w1.y;
    a.z = u.z - lam * w1.z; a.w = u.w - lam * w1.w;
    float ss = a.x * a.x + a.y * a.y + a.z * a.z + a.w * a.w;
#pragma unroll
    for (int o = 16; o > 0; o >>= 1) ss += __shfl_xor_sync(0xFFFFFFFFu, ss, o);
    float r = rsqrtf(ss * (1.f / 128.f) + EPS_RMS);
    const float4 w = *(const float4*)(subln + lane * 4);
    float y0 = a.x * r * w.x, y1 = a.y * r * w.y;
    float y2 = a.z * r * w.z, y3 = a.w * r * w.w;
    size_t off = (size_t)(b * Tt + t) * Ee + h * D2 + lane * 4;
    store_hl(g_yhi, g_ylo, off, y0, y1);
    store_hl(g_yhi, g_ylo, off + 2, y2, y3);
}

// ------------------------ launch ------------------------
extern "C" void kernel_launch(void* const* d_in, const int* in_sizes, int n_in,
                              void* d_out, int out_size) {
    const float* x       = (const float*)d_in[0];
    const float* rel_pos = (const float*)d_in[1];
    const float* wq      = (const float*)d_in[2];
    const float* wk      = (const float*)d_in[3];
    const float* wv      = (const float*)d_in[4];
    const float* lq1     = (const float*)d_in[5];
    const float* lq2     = (const float*)d_in[6];
    const float* lk1     = (const float*)d_in[7];
    const float* lk2     = (const float*)d_in[8];
    const float* subln   = (const float*)d_in[9];
    const float* wo      = (const float*)d_in[10];
    float* out = (float*)d_out;

    __nv_bfloat16 *xhi, *xlo, *whi, *wlo;
    cudaGetSymbolAddress((void**)&xhi, g_xhi);
    cudaGetSymbolAddress((void**)&xlo, g_xlo);
    cudaGetSymbolAddress((void**)&whi, g_whi);
    cudaGetSymbolAddress((void**)&wlo, g_wlo);

    cudaFuncSetAttribute(gemm_qkv, cudaFuncAttributeMaxDynamicSharedMemorySize, GSMEM);
    cudaFuncSetAttribute(gemm_out, cudaFuncAttributeMaxDynamicSharedMemorySize, GSMEM);
    cudaFuncSetAttribute(fattn_kernel, cudaFuncAttributeMaxDynamicSharedMemorySize, FA_SMEM_BYTES);

    const int n4 = Mm * Ee / 4;

    // position 4 = fused QKV gemm (ncu -s window captures launch #4)
    cvt_split<<<(n4 + 255) / 256, 256>>>(x, xhi, xlo, n4);                   // 1
    cvt_split4<<<(4 * n4 + 255) / 256, 256>>>(wq, wk, wv, wo, whi, wlo);     // 2
    rope_table<<<(Tt * 32 + 255) / 256, 256>>>();                            // 3
    gemm_qkv<<<dim3(3 * Ee / BN, Mm / BM), 256, GSMEM>>>();                  // 4
    lam_kernel<<<1, 64>>>(lq1, lq2, lk1, lk2);                               // 5

    int np2 = 2 * Bb * Tt * H2 * 32;
    rope_qk_kernel<<<(np2 + 255) / 256, 256>>>(rel_pos);

    fattn_kernel<<<dim3(Tt / 64, Bb * H2), 256, FA_SMEM_BYTES>>>();
    rms2_kernel<<<Bb * Hh * Tt / 8, 256>>>(subln);

    gemm_out<<<dim3(Ee / BN, Mm / BM), 256, GSMEM>>>(out);
}

// round 16
// speedup vs baseline: 1.4344x; 1.3121x over previous
#include <cuda_runtime.h>
#include <cuda_bf16.h>
#include <cuda_fp16.h>
#include <math.h>
#include <stdint.h>

// Problem constants
#define Bb 2
#define Tt 1024
#define Ee 2048
#define Hh 16
#define Dd 64
#define H2 32          // 2*H
#define D2 128         // 2*D
#define Mm (Bb*Tt)     // 2048
#define LAMBDA_INIT 0.78360576653162f
#define EPS_RMS 1e-5f

// ------------------------ scratch (static device memory) ------------------------
__device__ float g_qraw[(size_t)Mm*Ee];
__device__ float g_kraw[(size_t)Mm*Ee];
__device__ float g_oc[(size_t)Bb*H2*Tt*D2];   // per-component attention output
__device__ float g_lam[1];
__device__ float g_cos[Tt*32];
__device__ float g_sin[Tt*32];

// fp16 GEMM operands (A split hi/lo, weights single)
__device__ __half g_xhi[(size_t)Mm*Ee];
__device__ __half g_xlo[(size_t)Mm*Ee];
__device__ __half g_wh[(size_t)4*Ee*Ee];
__device__ __half g_yhi[(size_t)Mm*Ee];
__device__ __half g_ylo[(size_t)Mm*Ee];
// rope'd q/k in (B,2H,T,D), bf16 hi/lo split (attention path unchanged)
__device__ __nv_bfloat16 g_qhib[(size_t)Bb*H2*Tt*Dd];
__device__ __nv_bfloat16 g_qlob[(size_t)Bb*H2*Tt*Dd];
__device__ __nv_bfloat16 g_khib[(size_t)Bb*H2*Tt*Dd];
__device__ __nv_bfloat16 g_klob[(size_t)Bb*H2*Tt*Dd];
// v split in (b,t,e) -- written directly by the QKV GEMM epilogue (bf16)
__device__ __nv_bfloat16 g_vhib[(size_t)Mm*Ee];
__device__ __nv_bfloat16 g_vlob[(size_t)Mm*Ee];

// ------------------------ helpers ------------------------
__device__ __forceinline__ unsigned s2u(const void* p) {
    return (unsigned)__cvta_generic_to_shared(p);
}
__device__ __forceinline__ void cp16(unsigned saddr, const void* g) {
    asm volatile("cp.async.cg.shared.global [%0], [%1], 16;\n" :: "r"(saddr), "l"(g));
}
#define CP_COMMIT() asm volatile("cp.async.commit_group;\n" ::: "memory")
#define CP_WAIT0()  asm volatile("cp.async.wait_group 0;\n" ::: "memory")
#define CP_WAIT1()  asm volatile("cp.async.wait_group 1;\n" ::: "memory")

#define LDSM4(r, addr) \
    asm volatile("ldmatrix.sync.aligned.m8n8.x4.shared.b16 {%0,%1,%2,%3}, [%4];" \
        : "=r"((r)[0]), "=r"((r)[1]), "=r"((r)[2]), "=r"((r)[3]) : "r"(addr))
#define LDSM4T(r, addr) \
    asm volatile("ldmatrix.sync.aligned.m8n8.x4.trans.shared.b16 {%0,%1,%2,%3}, [%4];" \
        : "=r"((r)[0]), "=r"((r)[1]), "=r"((r)[2]), "=r"((r)[3]) : "r"(addr))

#define MMA_BF16(d, a, b) \
    asm volatile("mma.sync.aligned.m16n8k16.row.col.f32.bf16.bf16.f32 " \
        "{%0,%1,%2,%3}, {%4,%5,%6,%7}, {%8,%9}, {%0,%1,%2,%3};" \
        : "+f"((d)[0]), "+f"((d)[1]), "+f"((d)[2]), "+f"((d)[3]) \
        : "r"((a)[0]), "r"((a)[1]), "r"((a)[2]), "r"((a)[3]), "r"((b)[0]), "r"((b)[1]))

#define MMA_F16(d, a, b) \
    asm volatile("mma.sync.aligned.m16n8k16.row.col.f32.f16.f16.f32 " \
        "{%0,%1,%2,%3}, {%4,%5,%6,%7}, {%8,%9}, {%0,%1,%2,%3};" \
        : "+f"((d)[0]), "+f"((d)[1]), "+f"((d)[2]), "+f"((d)[3]) \
        : "r"((a)[0]), "r"((a)[1]), "r"((a)[2]), "r"((a)[3]), "r"((b)[0]), "r"((b)[1]))

__device__ __forceinline__ unsigned packbf(float a, float b) {
    unsigned short ua = __bfloat16_as_ushort(__float2bfloat16(a));
    unsigned short ub = __bfloat16_as_ushort(__float2bfloat16(b));
    return (unsigned)ua | ((unsigned)ub << 16);
}
// bf16 hi/lo split store (V path)
__device__ __forceinline__ void store_hl(__nv_bfloat16* hi, __nv_bfloat16* lo,
                                         size_t off, float a, float b) {
    __nv_bfloat16 ha = __float2bfloat16(a), hb = __float2bfloat16(b);
    unsigned hw = (unsigned)__bfloat16_as_ushort(ha) |
                  ((unsigned)__bfloat16_as_ushort(hb) << 16);
    unsigned lw = packbf(a - __bfloat162float(ha), b - __bfloat162float(hb));
    *(unsigned*)(hi + off) = hw;
    *(unsigned*)(lo + off) = lw;
}
// fp16 hi/lo split store (y path)
__device__ __forceinline__ void store_hl_h(__half* hi, __half* lo,
                                           size_t off, float a, float b) {
    __half ha = __float2half_rn(a), hb = __float2half_rn(b);
    __half la = __float2half_rn(a - __half2float(ha));
    __half lb = __float2half_rn(b - __half2float(hb));
    unsigned hw = (unsigned)__half_as_ushort(ha) | ((unsigned)__half_as_ushort(hb) << 16);
    unsigned lw = (unsigned)__half_as_ushort(la) | ((unsigned)__half_as_ushort(lb) << 16);
    *(unsigned*)(hi + off) = hw;
    *(unsigned*)(lo + off) = lw;
}

// ------------------------ fp32 -> fp16 hi/lo split (x) ------------------------
__global__ __launch_bounds__(256) void cvt_xh(const float* __restrict__ s,
                                              __half* __restrict__ hi,
                                              __half* __restrict__ lo, int n4) {
    int i = blockIdx.x * blockDim.x + threadIdx.x;
    if (i >= n4) return;
    float4 v = ((const float4*)s)[i];
    __half h0 = __float2half_rn(v.x), h1 = __float2half_rn(v.y);
    __half h2 = __float2half_rn(v.z), h3 = __float2half_rn(v.w);
    __half l0 = __float2half_rn(v.x - __half2float(h0));
    __half l1 = __float2half_rn(v.y - __half2float(h1));
    __half l2 = __float2half_rn(v.z - __half2float(h2));
    __half l3 = __float2half_rn(v.w - __half2float(h3));
    ushort4 hv, lv;
    hv.x = __half_as_ushort(h0); hv.y = __half_as_ushort(h1);
    hv.z = __half_as_ushort(h2); hv.w = __half_as_ushort(h3);
    lv.x = __half_as_ushort(l0); lv.y = __half_as_ushort(l1);
    lv.z = __half_as_ushort(l2); lv.w = __half_as_ushort(l3);
    ((ushort4*)hi)[i] = hv;
    ((ushort4*)lo)[i] = lv;
}

// all 4 weight matrices -> fp16 single, one launch (each 2^20 float4s)
__global__ __launch_bounds__(256) void cvt_w4h(
    const float* __restrict__ w0, const float* __restrict__ w1,
    const float* __restrict__ w2, const float* __restrict__ w3,
    __half* __restrict__ dst) {
    int idx = blockIdx.x * blockDim.x + threadIdx.x;   // 0 .. 4*2^20-1
    int sel = idx >> 20;
    int i = idx & ((1 << 20) - 1);
    const float* w = (sel == 0) ? w0 : (sel == 1) ? w1 : (sel == 2) ? w2 : w3;
    size_t off = (size_t)sel << 22;                    // sel * Ee*Ee elems
    float4 v = ((const float4*)w)[i];
    ushort4 hv;
    hv.x = __half_as_ushort(__float2half_rn(v.x));
    hv.y = __half_as_ushort(__float2half_rn(v.y));
    hv.z = __half_as_ushort(__float2half_rn(v.z));
    hv.w = __half_as_ushort(__float2half_rn(v.w));
    ((ushort4*)(dst + off))[i] = hv;
}

// ------------------------ fp16x2 GEMM core: acc += (Ahi+Alo)[M,K] @ B[N,K]^T tile ---------
// BM=BN=128, BK=32(fp16), 256 threads (8 warps 4x2), 2-stage cp.async, 2 CTAs/SM.
// R11-style pipeline: CP_WAIT1 depth-1, frag load -> mid-tile sync at kk=1 -> issue.
#define BM 128
#define BN 128
#define BKg 32
#define KP 40                    // padded fp16 row stride (80B): conflict-free ldmatrix
#define STG (3*128*KP)           // elems per stage: Ahi, Alo, B
#define GSMEM (2*STG*2)          // 61440 B

__device__ __forceinline__ void gemm_core(
    const __half* __restrict__ Ahi, const __half* __restrict__ Alo,
    const __half* __restrict__ B,
    int row0, int col0, int K,
    __half* sm, float acc[2][8][4])
{
    const int tid = threadIdx.x;
    const int lane = tid & 31, warp = tid >> 5;
    const int wm = (warp & 3) * 32, wn = (warp >> 2) * 64;
    const int lr = tid >> 2, lq = (tid & 3) * 8;

    const __half* gbase[3] = {Ahi, Alo, B};
    const int grow0[3] = {row0, row0, col0};

    auto issue = [&](int buf, int k0) {
        __half* s = sm + buf * STG;
#pragma unroll
        for (int a = 0; a < 3; a++) {
            const __half* g = gbase[a] + (size_t)(grow0[a] + lr) * K + k0 + lq;
            cp16(s2u(s + a * 128 * KP + lr * KP + lq), g);
            cp16(s2u(s + a * 128 * KP + (lr + 64) * KP + lq), g + (size_t)64 * K);
        }
        CP_COMMIT();
    };

    issue(0, 0);
    issue(1, BKg);

    const int niter = K / BKg;
    for (int it = 0; it < niter; it++) {
        if (it + 1 < niter) CP_WAIT1(); else CP_WAIT0();
        __syncthreads();                       // stage it&1 visible to all

        __half* s = sm + (it & 1) * STG;
        __half* sAhi = s;
        __half* sAlo = s + 128 * KP;
        __half* sB   = s + 2 * 128 * KP;

#pragma unroll
        for (int kk = 0; kk < 2; kk++) {
            unsigned afh[2][4], afl[2][4], bf[4][4];
#pragma unroll
            for (int mi = 0; mi < 2; mi++) {
                int r = wm + mi * 16 + (lane & 15);
                int c = kk * 16 + (lane >> 4) * 8;
                LDSM4(afh[mi], s2u(sAhi + r * KP + c));
                LDSM4(afl[mi], s2u(sAlo + r * KP + c));
            }
#pragma unroll
            for (int p = 0; p < 4; p++) {
                int r = wn + p * 16 + ((lane >> 4) & 1) * 8 + (lane & 7);
                int c = kk * 16 + ((lane >> 3) & 1) * 8;
                LDSM4(bf[p], s2u(sB + r * KP + c));
            }
            if (kk == 1) {
                __syncthreads();               // all reads of buf it&1 done
                if (it + 2 < niter) issue(it & 1, (it + 2) * BKg);
            }
            // pass 1: Ahi * B
#pragma unroll
            for (int mi = 0; mi < 2; mi++)
#pragma unroll
                for (int nj = 0; nj < 8; nj++)
                    MMA_F16(acc[mi][nj], afh[mi], &bf[nj >> 1][(nj & 1) * 2]);
            // pass 2: Alo * B
#pragma unroll
            for (int mi = 0; mi < 2; mi++)
#pragma unroll
                for (int nj = 0; nj < 8; nj++)
                    MMA_F16(acc[mi][nj], afl[mi], &bf[nj >> 1][(nj & 1) * 2]);
        }
    }
}

// fused QKV projection: N = 3*2048 over [wq; wk; wv] rows of g_wh
__global__ __launch_bounds__(256, 2) void gemm_qkv() {
    extern __shared__ __align__(16) __half sm[];
    const int row0 = blockIdx.y * BM, col0 = blockIdx.x * BN;
    const int lane = threadIdx.x & 31, warp = threadIdx.x >> 5;
    const int wm = (warp & 3) * 32, wn = (warp >> 2) * 64;

    float acc[2][8][4];
#pragma unroll
    for (int a = 0; a < 2; a++)
#pragma unroll
        for (int b = 0; b < 8; b++)
#pragma unroll
            for (int c = 0; c < 4; c++) acc[a][b][c] = 0.f;

    gemm_core(g_xhi, g_xlo, g_wh, row0, col0, Ee, sm, acc);

    const int sel = col0 >> 11;          // 0=Q 1=K 2=V
    const int nc0 = col0 & 2047;
#pragma unroll
    for (int mi = 0; mi < 2; mi++)
#pragma unroll
        for (int nj = 0; nj < 8; nj++) {
            int r = row0 + wm + mi * 16 + (lane >> 2);
            int c = nc0 + wn + nj * 8 + (lane & 3) * 2;
            if (sel == 0) {
                *(float2*)&g_qraw[(size_t)r * Ee + c] = make_float2(acc[mi][nj][0], acc[mi][nj][1]);
                *(float2*)&g_qraw[(size_t)(r + 8) * Ee + c] = make_float2(acc[mi][nj][2], acc[mi][nj][3]);
            } else if (sel == 1) {
                *(float2*)&g_kraw[(size_t)r * Ee + c] = make_float2(acc[mi][nj][0], acc[mi][nj][1]);
                *(float2*)&g_kraw[(size_t)(r + 8) * Ee + c] = make_float2(acc[mi][nj][2], acc[mi][nj][3]);
            } else {
                store_hl(g_vhib, g_vlob, (size_t)r * Ee + c, acc[mi][nj][0], acc[mi][nj][1]);
                store_hl(g_vhib, g_vlob, (size_t)(r + 8) * Ee + c, acc[mi][nj][2], acc[mi][nj][3]);
            }
        }
}

// output projection: y @ wo^T -> out (fp32)
__global__ __launch_bounds__(256, 2) void gemm_out(float* __restrict__ C) {
    extern __shared__ __align__(16) __half sm[];
    const int row0 = blockIdx.y * BM, col0 = blockIdx.x * BN;
    const int lane = threadIdx.x & 31, warp = threadIdx.x >> 5;
    const int wm = (warp & 3) * 32, wn = (warp >> 2) * 64;

    float acc[2][8][4];
#pragma unroll
    for (int a = 0; a < 2; a++)
#pragma unroll
        for (int b = 0; b < 8; b++)
#pragma unroll
            for (int c = 0; c < 4; c++) acc[a][b][c] = 0.f;

    const size_t WSZ = (size_t)Ee * Ee;
    gemm_core(g_yhi, g_ylo, g_wh + 3 * WSZ, row0, col0, Ee, sm, acc);

#pragma unroll
    for (int mi = 0; mi < 2; mi++)
#pragma unroll
        for (int nj = 0; nj < 8; nj++) {
            int r = row0 + wm + mi * 16 + (lane >> 2);
            int c = col0 + wn + nj * 8 + (lane & 3) * 2;
            *(float2*)&C[(size_t)r * Ee + c] = make_float2(acc[mi][nj][0], acc[mi][nj][1]);
            *(float2*)&C[(size_t)(r + 8) * Ee + c] = make_float2(acc[mi][nj][2], acc[mi][nj][3]);
        }
}

// ------------------------ lambda scalar ------------------------
__global__ void lam_kernel(const float* __restrict__ lq1, const float* __restrict__ lq2,
                           const float* __restrict__ lk1, const float* __restrict__ lk2) {
    __shared__ float s1[64], s2[64];
    int t = threadIdx.x;
    s1[t] = lq1[t] * lk1[t];
    s2[t] = lq2[t] * lk2[t];
    __syncthreads();
    for (int s = 32; s > 0; s >>= 1) {
        if (t < s) { s1[t] += s1[t + s]; s2[t] += s2[t + s]; }
        __syncthreads();
    }
    if (t == 0) g_lam[0] = expf(s1[0]) - expf(s2[0]) + LAMBDA_INIT;
}

// ------------------------ RoPE cos/sin table ------------------------
__global__ void rope_table() {
    int idx = blockIdx.x * blockDim.x + threadIdx.x;
    if (idx >= Tt * 32) return;
    int t = idx / 32, i = idx % 32;
    float invf = (float)exp(-((double)i / 32.0) * log(10000.0));
    float ang = (float)t * invf;
    g_cos[idx] = cosf(ang);
    g_sin[idx] = sinf(ang);
}

// ------------------------ rope q+k (merged) -> (B,2H,T,D) bf16 hi/lo ------------------------
__global__ void rope_qk_kernel(const float* __restrict__ rel_pos) {
    int idx = blockIdx.x * blockDim.x + threadIdx.x;
    const int np = Bb * Tt * H2 * 32;
    if (idx >= 2 * np) return;
    const bool isq = idx < np;
    if (!isq) idx -= np;
    int i = idx & 31;
    int hh = (idx >> 5) & (H2 - 1);
    int t = (idx >> 10) & (Tt - 1);
    int b = idx >> 20;
    size_t in = (size_t)(b * Tt + t) * Ee + hh * Dd + 2 * i;
    float x1, x2;
    if (isq) { x1 = g_qraw[in]; x2 = g_qraw[in + 1]; }
    else {
        x1 = g_kraw[in] * rel_pos[t * Dd + 2 * i];
        x2 = g_kraw[in + 1] * rel_pos[t * Dd + 2 * i + 1];
    }
    float c = g_cos[t * 32 + i], s = g_sin[t * 32 + i];
    float r1 = x1 * c - x2 * s;
    float r2 = x1 * s + x2 * c;
    size_t out = ((size_t)(b * H2 + hh) * Tt + t) * Dd + 2 * i;
    __nv_bfloat16 h1 = __float2bfloat16(r1), h2 = __float2bfloat16(r2);
    __nv_bfloat16 l1 = __float2bfloat16(r1 - __bfloat162float(h1));
    __nv_bfloat16 l2 = __float2bfloat16(r2 - __bfloat162float(h2));
    if (isq) {
        g_qhib[out] = h1; g_qhib[out + 1] = h2;
        g_qlob[out] = l1; g_qlob[out + 1] = l2;
    } else {
        g_khib[out] = h1; g_khib[out + 1] = h2;
        g_klob[out] = l1; g_klob[out + 1] = l2;
    }
}

// ------------------------ fused flash differential attention ------------------------
// single-buffer K/V (2 CTAs/SM); K reloaded after score-phase barrier, V after tile barrier.
#define FA_SMEM_ELE 45056
#define FA_SMEM_BYTES (FA_SMEM_ELE*2 + 448*4)

__global__ __launch_bounds__(256, 2) void fattn_kernel() {
    extern __shared__ __align__(16) __nv_bfloat16 fsm[];
    __nv_bfloat16* sQh = fsm;
    __nv_bfloat16* sQl = fsm + 4608;
    __nv_bfloat16* sKh = fsm + 9216;
    __nv_bfloat16* sKl = fsm + 13824;
    __nv_bfloat16* sVh = fsm + 18432;
    __nv_bfloat16* sVl = fsm + 27136;
    __nv_bfloat16* sPh = fsm + 35840;
    __nv_bfloat16* sPl = fsm + 40448;
    float* fst   = (float*)(fsm + FA_SMEM_ELE);
    float* sm_m  = fst;          // [64]
    float* sm_l  = fst + 64;
    float* sm_al = fst + 128;
    float* rmax  = fst + 192;    // [2][64]
    float* rsum  = fst + 320;    // [2][64]

    const int tid = threadIdx.x, lane = tid & 31, warp = tid >> 5;
    const int comp = blockIdx.y;
    const int b = comp >> 5;
    const int hh = comp & 31;
    const int qt = (int)gridDim.x - 1 - (int)blockIdx.x;   // heavy blocks first
    const int q0 = qt * 64;

    const __nv_bfloat16* qh = g_qhib + ((size_t)comp * Tt + q0) * Dd;
    const __nv_bfloat16* ql = g_qlob + ((size_t)comp * Tt + q0) * Dd;
    const __nv_bfloat16* kh = g_khib + (size_t)comp * Tt * Dd;
    const __nv_bfloat16* kl = g_klob + (size_t)comp * Tt * Dd;
    const __nv_bfloat16* vh = g_vhib + (size_t)b * Tt * Ee + (hh >> 1) * D2;
    const __nv_bfloat16* vl = g_vlob + (size_t)b * Tt * Ee + (hh >> 1) * D2;

    if (tid < 64) { sm_m[tid] = -1e30f; sm_l[tid] = 0.f; }

    auto load_k = [&](int jt) {
        const __nv_bfloat16* gkh = kh + (size_t)(jt * 64) * Dd;
        const __nv_bfloat16* gkl = kl + (size_t)(jt * 64) * Dd;
#pragma unroll
        for (int i = 0; i < 2; i++) {
            int ch = tid + i * 256, r = ch >> 3, c = (ch & 7) * 8;
            cp16(s2u(sKh + r * 72 + c), gkh + (size_t)r * Dd + c);
            cp16(s2u(sKl + r * 72 + c), gkl + (size_t)r * Dd + c);
        }
    };
    auto load_v = [&](int jt) {
        const __nv_bfloat16* gvh = vh + (size_t)(jt * 64) * Ee;
        const __nv_bfloat16* gvl = vl + (size_t)(jt * 64) * Ee;
#pragma unroll
        for (int i = 0; i < 4; i++) {
            int ch = tid + i * 256, r = ch >> 4, c = (ch & 15) * 8;
            cp16(s2u(sVh + r * 136 + c), gvh + (size_t)r * Ee + c);
            cp16(s2u(sVl + r * 136 + c), gvl + (size_t)r * Ee + c);
        }
    };

    // prologue: Q + K0 + V0 in one group
    {
#pragma unroll
        for (int i = 0; i < 2; i++) {
            int ch = tid + i * 256, r = ch >> 3, c = (ch & 7) * 8;
            cp16(s2u(sQh + r * 72 + c), qh + (size_t)r * Dd + c);
            cp16(s2u(sQl + r * 72 + c), ql + (size_t)r * Dd + c);
        }
        load_k(0);
        load_v(0);
        CP_COMMIT();
    }

    float O[2][4][4];
#pragma unroll
    for (int a = 0; a < 2; a++)
#pragma unroll
        for (int c = 0; c < 4; c++)
#pragma unroll
            for (int e = 0; e < 4; e++) O[a][c][e] = 0.f;

    const int wm = warp & 3, wn = warp >> 2;     // score view: m16 x n32
    const int wm2 = warp & 1, wn2 = warp >> 1;   // pv view:    m32 x n32
    const int njt = qt + 1;

    for (int jt = 0; jt < njt; jt++) {
        CP_WAIT0();
        __syncthreads();

        // ---- scores S = Q K^T (bf16x3)
        float S[4][4];
#pragma unroll
        for (int nf = 0; nf < 4; nf++)
#pragma unroll
            for (int e = 0; e < 4; e++) S[nf][e] = 0.f;
        {
            const int arow = wm * 16 + (lane & 7) + ((lane >> 3) & 1) * 8;
            const int brow = (lane >> 4) * 8 + (lane & 7);
#pragma unroll
            for (int ks = 0; ks < 4; ks++) {
                unsigned ah[4], al[4], bh0[4], bh1[4], bl0[4], bl1[4];
                int acol = ks * 16 + (lane >> 4) * 8;
                LDSM4(ah, s2u(sQh + arow * 72 + acol));
                LDSM4(al, s2u(sQl + arow * 72 + acol));
                int bcol = ks * 16 + ((lane >> 3) & 1) * 8;
                LDSM4(bh0, s2u(sKh + (wn * 32 + brow) * 72 + bcol));
                LDSM4(bh1, s2u(sKh + (wn * 32 + 16 + brow) * 72 + bcol));
                LDSM4(bl0, s2u(sKl + (wn * 32 + brow) * 72 + bcol));
                LDSM4(bl1, s2u(sKl + (wn * 32 + 16 + brow) * 72 + bcol));
#pragma unroll
                for (int nf = 0; nf < 4; nf++) {
                    const unsigned* bh = (nf < 2 ? bh0 : bh1) + (nf & 1) * 2;
                    const unsigned* bl = (nf < 2 ? bl0 : bl1) + (nf & 1) * 2;
                    MMA_BF16(S[nf], ah, bh);
                    MMA_BF16(S[nf], ah, bl);
                    MMA_BF16(S[nf], al, bh);
                }
            }
        }
        // ---- scale + causal mask
        const bool diag = (jt == qt);
        const int rl0 = wm * 16 + (lane >> 2);
#pragma unroll
        for (int nf = 0; nf < 4; nf++) {
            int cl = wn * 32 + nf * 8 + (lane & 3) * 2;
#pragma unroll
            for (int hn = 0; hn < 2; hn++)
#pragma unroll
                for (int e = 0; e < 2; e++) {
                    float s = S[nf][hn * 2 + e] * 0.125f;
                    if (diag && (cl + e > rl0 + hn * 8)) s = -1e30f;
                    S[nf][hn * 2 + e] = s;
                }
        }
        // ---- row max (partial within warp cols)
        {
            float mx0 = -1e30f, mx1 = -1e30f;
#pragma unroll
            for (int nf = 0; nf < 4; nf++) {
                mx0 = fmaxf(mx0, fmaxf(S[nf][0], S[nf][1]));
                mx1 = fmaxf(mx1, fmaxf(S[nf][2], S[nf][3]));
            }
            mx0 = fmaxf(mx0, __shfl_xor_sync(0xFFFFFFFFu, mx0, 1));
            mx0 = fmaxf(mx0, __shfl_xor_sync(0xFFFFFFFFu, mx0, 2));
            mx1 = fmaxf(mx1, __shfl_xor_sync(0xFFFFFFFFu, mx1, 1));
            mx1 = fmaxf(mx1, __shfl_xor_sync(0xFFFFFFFFu, mx1, 2));
            if ((lane & 3) == 0) {
                rmax[wn * 64 + rl0] = mx0;
                rmax[wn * 64 + rl0 + 8] = mx1;
            }
        }
        __syncthreads();   // A: all K reads + rmax writes done
        if (jt + 1 < njt) { load_k(jt + 1); CP_COMMIT(); }   // K reload overlaps softmax+PV
        if (tid < 64) {
            float mo = sm_m[tid];
            float mn = fmaxf(mo, fmaxf(rmax[tid], rmax[64 + tid]));
            sm_m[tid] = mn;
            sm_al[tid] = __expf(mo - mn);
        }
        __syncthreads();   // B
        // ---- p = exp(S - m), row sums, store P hi/lo to smem
        {
            float mrow0 = sm_m[rl0], mrow1 = sm_m[rl0 + 8];
            float s0 = 0.f, s1 = 0.f;
#pragma unroll
            for (int nf = 0; nf < 4; nf++) {
                int cl = wn * 32 + nf * 8 + (lane & 3) * 2;
                float p00 = __expf(S[nf][0] - mrow0);
                float p01 = __expf(S[nf][1] - mrow0);
                float p10 = __expf(S[nf][2] - mrow1);
                float p11 = __expf(S[nf][3] - mrow1);
                s0 += p00 + p01; s1 += p10 + p11;
                float h00 = __bfloat162float(__float2bfloat16(p00));
                float h01 = __bfloat162float(__float2bfloat16(p01));
                float h10 = __bfloat162float(__float2bfloat16(p10));
                float h11 = __bfloat162float(__float2bfloat16(p11));
                *(unsigned*)(sPh + rl0 * 72 + cl)       = packbf(h00, h01);
                *(unsigned*)(sPh + (rl0 + 8) * 72 + cl) = packbf(h10, h11);
                *(unsigned*)(sPl + rl0 * 72 + cl)       = packbf(p00 - h00, p01 - h01);
                *(unsigned*)(sPl + (rl0 + 8) * 72 + cl) = packbf(p10 - h10, p11 - h11);
            }
            s0 += __shfl_xor_sync(0xFFFFFFFFu, s0, 1);
            s0 += __shfl_xor_sync(0xFFFFFFFFu, s0, 2);
            s1 += __shfl_xor_sync(0xFFFFFFFFu, s1, 1);
            s1 += __shfl_xor_sync(0xFFFFFFFFu, s1, 2);
            if ((lane & 3) == 0) {
                rsum[wn * 64 + rl0] = s0;
                rsum[wn * 64 + rl0 + 8] = s1;
            }
        }
        __syncthreads();   // C
        if (tid < 64) sm_l[tid] = sm_l[tid] * sm_al[tid] + rsum[tid] + rsum[64 + tid];
        // ---- rescale O
        {
            const int orow = wm2 * 32 + (lane >> 2);
#pragma unroll
            for (int mf = 0; mf < 2; mf++) {
                float a0 = sm_al[orow + mf * 16];
                float a1 = sm_al[orow + mf * 16 + 8];
#pragma unroll
                for (int nf = 0; nf < 4; nf++) {
                    O[mf][nf][0] *= a0; O[mf][nf][1] *= a0;
                    O[mf][nf][2] *= a1; O[mf][nf][3] *= a1;
                }
            }
        }
        // ---- O += P V (bf16x3), V^T via ldmatrix.trans
        {
            const int prow0 = wm2 * 32 + (lane & 7) + ((lane >> 3) & 1) * 8;
            const int vcol = wn2 * 32 + (lane >> 4) * 8;
#pragma unroll
            for (int ks = 0; ks < 4; ks++) {
                unsigned pah[2][4], pal[2][4], vh0[4], vh1[4], vl0[4], vl1[4];
                int pcol = ks * 16 + (lane >> 4) * 8;
#pragma unroll
                for (int mf = 0; mf < 2; mf++) {
                    LDSM4(pah[mf], s2u(sPh + (prow0 + mf * 16) * 72 + pcol));
                    LDSM4(pal[mf], s2u(sPl + (prow0 + mf * 16) * 72 + pcol));
                }
                int vrow = ks * 16 + ((lane >> 3) & 1) * 8 + (lane & 7);
                LDSM4T(vh0, s2u(sVh + vrow * 136 + vcol));
                LDSM4T(vh1, s2u(sVh + vrow * 136 + vcol + 16));
                LDSM4T(vl0, s2u(sVl + vrow * 136 + vcol));
                LDSM4T(vl1, s2u(sVl + vrow * 136 + vcol + 16));
#pragma unroll
                for (int mf = 0; mf < 2; mf++)
#pragma unroll
                    for (int nf = 0; nf < 4; nf++) {
                        const unsigned* bh = (nf < 2 ? vh0 : vh1) + (nf & 1) * 2;
                        const unsigned* bl = (nf < 2 ? vl0 : vl1) + (nf & 1) * 2;
                        MMA_BF16(O[mf][nf], pah[mf], bh);
                        MMA_BF16(O[mf][nf], pah[mf], bl);
                        MMA_BF16(O[mf][nf], pal[mf], bh);
                    }
            }
        }
        __syncthreads();   // D: all V/P reads done
        if (jt + 1 < njt) { load_v(jt + 1); CP_COMMIT(); }   // V reload
    }

    // ---- epilogue: O / l -> g_oc (comp, t, 128)
    {
        const int orow = wm2 * 32 + (lane >> 2);
#pragma unroll
        for (int mf = 0; mf < 2; mf++) {
            int r0 = orow + mf * 16, r1 = r0 + 8;
            float li0 = 1.f / sm_l[r0];
            float li1 = 1.f / sm_l[r1];
#pragma unroll
            for (int nf = 0; nf < 4; nf++) {
                int col = wn2 * 32 + nf * 8 + (lane & 3) * 2;
                *(float2*)&g_oc[((size_t)comp * Tt + q0 + r0) * D2 + col] =
                    make_float2(O[mf][nf][0] * li0, O[mf][nf][1] * li0);
                *(float2*)&g_oc[((size_t)comp * Tt + q0 + r1) * D2 + col] =
                    make_float2(O[mf][nf][2] * li1, O[mf][nf][3] * li1);
            }
        }
    }
}

// ------------------------ combine + RMS norm + subln -> fp16 hi/lo y ------------------------
__global__ __launch_bounds__(256) void rms2_kernel(const float* __restrict__ subln) {
    const int warp = threadIdx.x >> 5, lane = threadIdx.x & 31;
    const size_t row = (size_t)blockIdx.x * 8 + warp;   // over B*H*T
    int t = (int)(row & (Tt - 1));
    int h = (int)((row >> 10) & (Hh - 1));
    int b = (int)(row >> 14);
    const float lam = g_lam[0];
    const float* o0 = g_oc + ((size_t)(b * H2 + 2 * h) * Tt + t) * D2 + lane * 4;
    const float* o1 = o0 + (size_t)Tt * D2;
    float4 u = *(const float4*)o0;
    float4 w1 = *(const float4*)o1;
    float4 a;
    a.x = u.x - lam * w1.x; a.y = u.y - lam * w1.y;
    a.z = u.z - lam * w1.z; a.w = u.w - lam * w1.w;
    float ss = a.x * a.x + a.y * a.y + a.z * a.z + a.w * a.w;
#pragma unroll
    for (int o = 16; o > 0; o >>= 1) ss += __shfl_xor_sync(0xFFFFFFFFu, ss, o);
    float r = rsqrtf(ss * (1.f / 128.f) + EPS_RMS);
    const float4 w = *(const float4*)(subln + lane * 4);
    float y0 = a.x * r * w.x, y1 = a.y * r * w.y;
    float y2 = a.z * r * w.z, y3 = a.w * r * w.w;
    size_t off = (size_t)(b * Tt + t) * Ee + h * D2 + lane * 4;
    store_hl_h(g_yhi, g_ylo, off, y0, y1);
    store_hl_h(g_yhi, g_ylo, off + 2, y2, y3);
}

// ------------------------ launch ------------------------
extern "C" void kernel_launch(void* const* d_in, const int* in_sizes, int n_in,
                              void* d_out, int out_size) {
    const float* x       = (const float*)d_in[0];
    const float* rel_pos = (const float*)d_in[1];
    const float* wq      = (const float*)d_in[2];
    const float* wk      = (const float*)d_in[3];
    const float* wv      = (const float*)d_in[4];
    const float* lq1     = (const float*)d_in[5];
    const float* lq2     = (const float*)d_in[6];
    const float* lk1     = (const float*)d_in[7];
    const float* lk2     = (const float*)d_in[8];
    const float* subln   = (const float*)d_in[9];
    const float* wo      = (const float*)d_in[10];
    float* out = (float*)d_out;

    __half *xhi, *xlo, *wh;
    cudaGetSymbolAddress((void**)&xhi, g_xhi);
    cudaGetSymbolAddress((void**)&xlo, g_xlo);
    cudaGetSymbolAddress((void**)&wh, g_wh);

    cudaFuncSetAttribute(gemm_qkv, cudaFuncAttributeMaxDynamicSharedMemorySize, GSMEM);
    cudaFuncSetAttribute(gemm_out, cudaFuncAttributeMaxDynamicSharedMemorySize, GSMEM);
    cudaFuncSetAttribute(fattn_kernel, cudaFuncAttributeMaxDynamicSharedMemorySize, FA_SMEM_BYTES);

    const int n4 = Mm * Ee / 4;

    // position 4 = fused QKV gemm (ncu -s window captures launch #4)
    cvt_xh<<<(n4 + 255) / 256, 256>>>(x, xhi, xlo, n4);                      // 1
    cvt_w4h<<<(4 * n4 + 255) / 256, 256>>>(wq, wk, wv, wo, wh);              // 2
    rope_table<<<(Tt * 32 + 255) / 256, 256>>>();                            // 3
    gemm_qkv<<<dim3(3 * Ee / BN, Mm / BM), 256, GSMEM>>>();                  // 4
    lam_kernel<<<1, 64>>>(lq1, lq2, lk1, lk2);                               // 5

    int np2 = 2 * Bb * Tt * H2 * 32;
    rope_qk_kernel<<<(np2 + 255) / 256, 256>>>(rel_pos);

    fattn_kernel<<<dim3(Tt / 64, Bb * H2), 256, FA_SMEM_BYTES>>>();
    rms2_kernel<<<Bb * Hh * Tt / 8, 256>>>(subln);

    gemm_out<<<dim3(Ee / BN, Mm / BM), 256, GSMEM>>>(out);
}